// round 15
// baseline (speedup 1.0000x reference)
#include <cuda_runtime.h>
#include <cuda_fp16.h>
#include <cstdint>

// Problem constants
#define NB   4
#define CIN  256
#define HH   128
#define WW   128
#define HWP  (HH*WW)      // 16384
#define CO   512
#define TT   4096         // 64*64 output pixels
#define EPSF 1e-5f
#define ITERS 3

// ---------------------------------------------------------------------------
// Scratch
// ---------------------------------------------------------------------------
__device__ float g_q[(size_t)NB*TT*CO];    // staging: conv/qk/upd/mlp outputs

// fp16 split operands (x_out lives ONLY as hi/lo pair; x = hi + lo to ~2^-24)
__device__ __align__(16) __half g_xph[(size_t)NB*HWP*CIN];  // x_in hi, pixel-major [b][pix][c]
__device__ __align__(16) __half g_xpl[(size_t)NB*HWP*CIN];  // x_in lo
__device__ __align__(16) __half g_xh[(size_t)NB*TT*CO];     // x_out hi, M-major [b][t][c]
__device__ __align__(16) __half g_xl[(size_t)NB*TT*CO];     // x_out lo
__device__ __align__(16) __half g_yh[(size_t)NB*TT*CIN];    // y hi, [b][t][j]
__device__ __align__(16) __half g_yl[(size_t)NB*TT*CIN];    // y lo
// weights: conv (reordered [n][w*256+c]) | v | mlp  ([n][k] row-major)
#define OFF_CONV 0
#define OFF_V    (512*1024)
#define OFF_MLP  (OFF_V + 512*256)
#define W_TOTAL  (OFF_MLP + 512*512)
__device__ __align__(16) __half g_wh[W_TOTAL];
__device__ __align__(16) __half g_wl[W_TOTAL];
// W2 = K_w^T Q_w (256 x 512) split, + c = K_w^T q_b
__device__ __align__(16) __half g_w2h[256*512];
__device__ __align__(16) __half g_w2l[256*512];
__device__ float g_cvec[256];

// ===========================================================================
// helpers
// ===========================================================================
__device__ __forceinline__ uint32_t smem_to_u32(const void* p) {
    uint32_t a;
    asm("{ .reg .u64 t; cvta.to.shared.u64 t, %1; cvt.u32.u64 %0, t; }"
        : "=r"(a) : "l"(p));
    return a;
}
__device__ __forceinline__ float warp_sum(float v) {
#pragma unroll
    for (int o = 16; o > 0; o >>= 1) v += __shfl_xor_sync(0xffffffffu, v, o);
    return v;
}
__device__ __forceinline__ void mma16816(float* c, const uint32_t* a, const uint32_t* b) {
    asm("mma.sync.aligned.m16n8k16.row.col.f32.f16.f16.f32 "
        "{%0,%1,%2,%3}, {%4,%5,%6,%7}, {%8,%9}, {%0,%1,%2,%3};"
        : "+f"(c[0]), "+f"(c[1]), "+f"(c[2]), "+f"(c[3])
        : "r"(a[0]), "r"(a[1]), "r"(a[2]), "r"(a[3]), "r"(b[0]), "r"(b[1]));
}
__device__ __forceinline__ void ldsm4(uint32_t* r, uint32_t a) {
    asm("ldmatrix.sync.aligned.m8n8.x4.shared.b16 {%0,%1,%2,%3}, [%4];"
        : "=r"(r[0]), "=r"(r[1]), "=r"(r[2]), "=r"(r[3]) : "r"(a) : "memory");
}
__device__ __forceinline__ void cp16(uint32_t sm, const void* g) {
    asm volatile("cp.async.cg.shared.global [%0], [%1], 16;"
        :: "r"(sm), "l"(g) : "memory");
}
__device__ __forceinline__ void cp_commit() {
    asm volatile("cp.async.commit_group;" ::: "memory");
}
template<int N> __device__ __forceinline__ void cp_wait() {
    asm volatile("cp.async.wait_group %0;" :: "n"(N) : "memory");
}
__device__ __forceinline__ void split1f(float x, __half& h, __half& l) {
    h = __float2half_rn(x);
    l = __float2half_rn(x - __half2float(h));
}
__device__ __forceinline__ void split4f(float4 f, uint2& H, uint2& L) {
    __half h[4], l[4];
    split1f(f.x, h[0], l[0]); split1f(f.y, h[1], l[1]);
    split1f(f.z, h[2], l[2]); split1f(f.w, h[3], l[3]);
    __half2 h0 = __halves2half2(h[0], h[1]), h1 = __halves2half2(h[2], h[3]);
    __half2 l0 = __halves2half2(l[0], l[1]), l1 = __halves2half2(l[2], l[3]);
    H.x = *(uint32_t*)&h0; H.y = *(uint32_t*)&h1;
    L.x = *(uint32_t*)&l0; L.y = *(uint32_t*)&l1;
}
__device__ __forceinline__ float4 join4f(uint2 H, uint2 L) {
    __half2 h0 = *(__half2*)&H.x, h1 = *(__half2*)&H.y;
    __half2 l0 = *(__half2*)&L.x, l1 = *(__half2*)&L.y;
    float4 f;
    f.x = __half2float(__low2half(h0))  + __half2float(__low2half(l0));
    f.y = __half2float(__high2half(h0)) + __half2float(__high2half(l0));
    f.z = __half2float(__low2half(h1))  + __half2float(__low2half(l1));
    f.w = __half2float(__high2half(h1)) + __half2float(__high2half(l1));
    return f;
}

// ===========================================================================
// setup kernels
// ===========================================================================
// conv region reordered: W[n][w*256+c] = conv_w[n][c*4+w]
__global__ __launch_bounds__(256)
void split_w3(const float* __restrict__ w0, const float* __restrict__ w1,
              const float* __restrict__ w2)
{
    int i = blockIdx.x * 256 + threadIdx.x;
    if (i >= W_TOTAL) return;
    const float* s; int off;
    if (i < OFF_V) {
        int n = i >> 10, k = i & 1023;
        int w = k >> 8, cc = k & 255;
        s = w0; off = n * 1024 + cc * 4 + w;
    }
    else if (i < OFF_MLP) { s = w1; off = i - OFF_V; }
    else                  { s = w2; off = i - OFF_MLP; }
    __half h, l; split1f(s[off], h, l);
    g_wh[i] = h; g_wl[i] = l;
}

// x_in (NCHW) -> pixel-major fp16 hi/lo, one pass.
__global__ __launch_bounds__(256)
void split_xp(const float* __restrict__ x)
{
    __shared__ float sm[64][33];
    const int p0 = blockIdx.x * 32;
    const int c0 = blockIdx.y * 64;
    const int b  = blockIdx.z;
    const float* xb = x + ((size_t)b * CIN + c0) * HWP + p0;
    const int tx = threadIdx.x & 31, ty = threadIdx.x >> 5;   // 32 x 8
#pragma unroll
    for (int cc = ty; cc < 64; cc += 8)
        sm[cc][tx] = xb[(size_t)cc * HWP + tx];
    __syncthreads();
    const int cp = tx, pg = ty;
#pragma unroll
    for (int p = pg; p < 32; p += 8) {
        float f0 = sm[2 * cp][p], f1 = sm[2 * cp + 1][p];
        __half h0, l0, h1, l1; split1f(f0, h0, l0); split1f(f1, h1, l1);
        __half2 H = __halves2half2(h0, h1), L = __halves2half2(l0, l1);
        size_t o = ((size_t)b * HWP + p0 + p) * CIN + c0;
        ((uint32_t*)(g_xph + o))[cp] = *(uint32_t*)&H;
        ((uint32_t*)(g_xpl + o))[cp] = *(uint32_t*)&L;
    }
}

// W2[j][f] = sum_o K_w[o][j] * Q_w[o][f], split to fp16 hi/lo; c = K_w^T q_b.
__global__ __launch_bounds__(256)
void w2_kernel(const float* __restrict__ Kw, const float* __restrict__ Qw,
               const float* __restrict__ qb)
{
    __shared__ float Ks[32][33], Qs[32][33];
    const int j0 = blockIdx.x * 32, f0 = blockIdx.y * 32;
    const int txx = threadIdx.x & 15, tyy = threadIdx.x >> 4;
    float acc[2][2] = {{0.f, 0.f}, {0.f, 0.f}};
    for (int o0 = 0; o0 < 512; o0 += 32) {
#pragma unroll
        for (int l = threadIdx.x; l < 1024; l += 256) {
            int oo = l >> 5, jj = l & 31;
            Ks[oo][jj] = Kw[(size_t)(o0 + oo) * 256 + j0 + jj];
            Qs[oo][jj] = Qw[(size_t)(o0 + oo) * 512 + f0 + jj];
        }
        __syncthreads();
#pragma unroll
        for (int oo = 0; oo < 32; ++oo) {
            float k0 = Ks[oo][tyy * 2], k1 = Ks[oo][tyy * 2 + 1];
            float q0 = Qs[oo][txx * 2], q1 = Qs[oo][txx * 2 + 1];
            acc[0][0] += k0 * q0; acc[0][1] += k0 * q1;
            acc[1][0] += k1 * q0; acc[1][1] += k1 * q1;
        }
        __syncthreads();
    }
#pragma unroll
    for (int a = 0; a < 2; a++)
#pragma unroll
        for (int bb = 0; bb < 2; bb++) {
            int j = j0 + tyy * 2 + a, f = f0 + txx * 2 + bb;
            __half h, l; split1f(acc[a][bb], h, l);
            g_w2h[(size_t)j * 512 + f] = h;
            g_w2l[(size_t)j * 512 + f] = l;
        }
    if (blockIdx.y == 0 && threadIdx.x < 32) {
        int j = j0 + threadIdx.x;
        float s = 0.f;
        for (int o = 0; o < 512; ++o) s += Kw[(size_t)o * 256 + j] * qb[o];
        g_cvec[j] = s;
    }
}

// ===========================================================================
// HMMA split-fp16 GEMM core (tile 128x128, K-chunk 32, 8 warps 2x4,
// warp tile 64x32, 3-stage cp.async).
// Compute split per-ks; cp.async issue lands mid-chunk. Within a ks the hh
// sweep is mt-pipelined: A[mt+1] LDSM issued between mt's MMAs, so the first
// MMA starts after 6 LDSM instead of 20. Per-acc order hh->hl->lh unchanged.
// ===========================================================================
#define STAGE   32768
#define SMEMDYN (3*STAGE)

// M-major A loader + B loader (q/mlp/qk/upd GEMMs)
template<int K>
__device__ __forceinline__ void gemm_issue(
    uint32_t sb, int s, int c, int tid, int m0, int n0,
    const __half* pAh, const __half* pAl,
    const __half* Bh, const __half* Bl)
{
    const int k0 = c * 32;
    const uint32_t As = sb + s * STAGE;
    const uint32_t Bs = As + 16384;
#pragma unroll
    for (int j = 0; j < 4; j++) {
        int idx = tid + j * 256;
        int r = idx >> 3, q = idx & 7;
        uint32_t sm = As + r * 128 + ((q ^ (r & 7)) << 4);
        const __half* g = ((q < 4) ? pAh : pAl)
                          + (size_t)(m0 + r) * K + k0 + (q & 3) * 8;
        cp16(sm, g);
    }
#pragma unroll
    for (int j = 0; j < 4; j++) {
        int idx = tid + j * 256;
        int r = idx >> 3, q = idx & 7;
        uint32_t sm = Bs + r * 128 + ((q ^ (r & 7)) << 4);
        const __half* g = ((q < 4) ? Bh : Bl)
                          + (size_t)(n0 + r) * K + k0 + (q & 3) * 8;
        cp16(sm, g);
    }
    cp_commit();
}

// conv A loader: A[t][k], k = w*256 + cch; reads pixel-major xph/xpl directly.
__device__ __forceinline__ void gemm_issue_conv(
    uint32_t sb, int s, int c, int tid,
    const size_t* pbase,               // [4] per-j row base offsets (halves)
    const __half* xph, const __half* xpl,
    const __half* Bh, const __half* Bl, int n0)
{
    const int k0 = c * 32;
    const int w = c >> 3;              // window pixel index 0..3
    const size_t woff = (size_t)(w >> 1) * ((size_t)WW * CIN)
                      + (size_t)(w & 1) * CIN;
    const int cb = (c & 7) * 32;       // channel base within pixel
    const uint32_t As = sb + s * STAGE;
    const uint32_t Bs = As + 16384;
#pragma unroll
    for (int j = 0; j < 4; j++) {
        int idx = tid + j * 256;
        int r = idx >> 3, q = idx & 7;   // r = (tid>>3) + 32j, q = tid&7
        uint32_t sm = As + r * 128 + ((q ^ (r & 7)) << 4);
        const __half* g = ((q < 4) ? xph : xpl)
                          + pbase[j] + woff + cb + (q & 3) * 8;
        cp16(sm, g);
    }
#pragma unroll
    for (int j = 0; j < 4; j++) {
        int idx = tid + j * 256;
        int r = idx >> 3, q = idx & 7;
        uint32_t sm = Bs + r * 128 + ((q ^ (r & 7)) << 4);
        const __half* g = ((q < 4) ? Bh : Bl)
                          + (size_t)(n0 + r) * 1024 + k0 + (q & 3) * 8;
        cp16(sm, g);
    }
    cp_commit();
}

template<int KS>
__device__ __forceinline__ void gemm_compute_ks(
    uint32_t sb, int s, int lane, int wm, int wn, float acc[4][4][4])
{
    const uint32_t As = sb + s * STAGE;
    const uint32_t Bs = As + 16384;
    const int g = lane >> 3;
    const uint32_t l7 = lane & 7;
    uint32_t bh[8], bl[8], ah[16], al[16];
    // B fragments first (needed by every MMA)
    {
        uint32_t nrow = wn * 32 + (g >> 1) * 8 + l7;
        uint32_t cH = ((KS * 2 + (g & 1)) ^ l7) << 4;
        uint32_t cL = ((KS * 2 + (g & 1) + 4) ^ l7) << 4;
        uint32_t r0 = Bs + nrow * 128;
        ldsm4(&bh[0], r0 + cH);
        ldsm4(&bl[0], r0 + cL);
        uint32_t r1 = r0 + 16 * 128;
        ldsm4(&bh[4], r1 + cH);
        ldsm4(&bl[4], r1 + cL);
    }
    const uint32_t ch = KS * 2 + (g >> 1);
    auto loadA = [&](int mt) {
        uint32_t mrow = wm * 64 + mt * 16 + (g & 1) * 8 + l7;
        uint32_t ra = As + mrow * 128;
        ldsm4(&ah[mt * 4], ra + ((ch ^ l7) << 4));
        ldsm4(&al[mt * 4], ra + (((ch + 4) ^ l7) << 4));
    };
    // mt-pipelined hh sweep: prefetch A[mt+1] between mt's MMAs
    loadA(0);
#pragma unroll
    for (int mt = 0; mt < 4; ++mt) {
        if (mt < 3) loadA(mt + 1);
#pragma unroll
        for (int nt = 0; nt < 4; ++nt) mma16816(acc[mt][nt], &ah[mt * 4], &bh[nt * 2]);
    }
#pragma unroll
    for (int mt = 0; mt < 4; ++mt)
#pragma unroll
        for (int nt = 0; nt < 4; ++nt) mma16816(acc[mt][nt], &ah[mt * 4], &bl[nt * 2]);
#pragma unroll
    for (int mt = 0; mt < 4; ++mt)
#pragma unroll
        for (int nt = 0; nt < 4; ++nt) mma16816(acc[mt][nt], &al[mt * 4], &bh[nt * 2]);
}

__device__ __forceinline__ void gemm_epilogue(
    float acc[4][4][4], const float* bias, float* C,
    int lane, int wm, int wn, int m0, int n0, size_t bM, int ldc)
{
    const int gq = lane >> 2, tq = lane & 3;
#pragma unroll
    for (int mt = 0; mt < 4; ++mt) {
        int mrow = m0 + wm * 64 + mt * 16 + gq;
        float* Cr = C + (bM + mrow) * ldc + n0;
#pragma unroll
        for (int nt = 0; nt < 4; ++nt) {
            int col = wn * 32 + nt * 8 + tq * 2;
            float b0 = bias[n0 + col], b1 = bias[n0 + col + 1];
            float2 v0; v0.x = acc[mt][nt][0] + b0; v0.y = acc[mt][nt][1] + b1;
            *(float2*)&Cr[col] = v0;
            float2 v1; v1.x = acc[mt][nt][2] + b0; v1.y = acc[mt][nt][3] + b1;
            *(float2*)&Cr[col + 8 * ldc] = v1;
        }
    }
}

template<int NCH>
__global__ __launch_bounds__(256, 2)
void hgemm(const __half* __restrict__ Ah, const __half* __restrict__ Al,
           const __half* __restrict__ Bh, const __half* __restrict__ Bl,
           const float* __restrict__ bias, float* __restrict__ C,
           int M, int ldc)
{
    constexpr int K = NCH * 32;
    extern __shared__ char sm_[];
    const uint32_t sb = smem_to_u32(sm_);
    const int tid = threadIdx.x;
    const int lane = tid & 31;
    const int wid = tid >> 5;
    const int wm = wid & 1, wn = wid >> 1;
    const int m0 = blockIdx.x * 128, n0 = blockIdx.y * 128, bz = blockIdx.z;
    const __half* pAh = Ah + (size_t)bz * M * K;
    const __half* pAl = Al + (size_t)bz * M * K;

    float acc[4][4][4];
#pragma unroll
    for (int i = 0; i < 4; i++)
#pragma unroll
        for (int j = 0; j < 4; j++)
#pragma unroll
            for (int r = 0; r < 4; r++) acc[i][j][r] = 0.f;

    gemm_issue<K>(sb, 0, 0, tid, m0, n0, pAh, pAl, Bh, Bl);
    gemm_issue<K>(sb, 1, 1, tid, m0, n0, pAh, pAl, Bh, Bl);
#pragma unroll
    for (int c = 0; c < NCH; ++c) {
        if (c < NCH - 1) cp_wait<1>(); else cp_wait<0>();
        __syncthreads();
        gemm_compute_ks<0>(sb, c % 3, lane, wm, wn, acc);
        if (c + 2 < NCH) gemm_issue<K>(sb, (c + 2) % 3, c + 2, tid, m0, n0, pAh, pAl, Bh, Bl);
        gemm_compute_ks<1>(sb, c % 3, lane, wm, wn, acc);
    }
    gemm_epilogue(acc, bias, C, lane, wm, wn, m0, n0, (size_t)bz * M, ldc);
}

// conv GEMM: A gathered from pixel-major x_in (k = w*256 + c), K=1024.
__global__ __launch_bounds__(256, 2)
void hgemm_conv(const __half* __restrict__ xph, const __half* __restrict__ xpl,
                const __half* __restrict__ Bh, const __half* __restrict__ Bl,
                const float* __restrict__ bias, float* __restrict__ C)
{
    constexpr int NCH = 32;
    extern __shared__ char sm_[];
    const uint32_t sb = smem_to_u32(sm_);
    const int tid = threadIdx.x;
    const int lane = tid & 31;
    const int wid = tid >> 5;
    const int wm = wid & 1, wn = wid >> 1;
    const int m0 = blockIdx.x * 128, n0 = blockIdx.y * 128, bz = blockIdx.z;

    // per-j (4 A rows per thread: r = tid>>3 + 32j) top-left pixel bases
    size_t pbase[4];
    {
        int r0 = tid >> 3;
#pragma unroll
        for (int j = 0; j < 4; ++j) {
            int t = m0 + r0 + j * 32, ho = t >> 6, wo = t & 63;
            int pix = (ho << 1) * WW + (wo << 1);
            pbase[j] = ((size_t)bz * HWP + pix) * CIN;
        }
    }

    float acc[4][4][4];
#pragma unroll
    for (int i = 0; i < 4; i++)
#pragma unroll
        for (int j = 0; j < 4; j++)
#pragma unroll
            for (int r = 0; r < 4; r++) acc[i][j][r] = 0.f;

    gemm_issue_conv(sb, 0, 0, tid, pbase, xph, xpl, Bh, Bl, n0);
    gemm_issue_conv(sb, 1, 1, tid, pbase, xph, xpl, Bh, Bl, n0);
#pragma unroll
    for (int c = 0; c < NCH; ++c) {
        if (c < NCH - 1) cp_wait<1>(); else cp_wait<0>();
        __syncthreads();
        gemm_compute_ks<0>(sb, c % 3, lane, wm, wn, acc);
        if (c + 2 < NCH) gemm_issue_conv(sb, (c + 2) % 3, c + 2, tid, pbase, xph, xpl, Bh, Bl, n0);
        gemm_compute_ks<1>(sb, c % 3, lane, wm, wn, acc);
    }
    gemm_epilogue(acc, bias, C, lane, wm, wn, m0, n0, (size_t)bz * TT, CO);
}

// ---------------------------------------------------------------------------
// Channel LayerNorm over CO=512, float4-vectorized, 128 threads/row (R13 form).
// x_out lives as fp16 hi/lo pair; add-path reconstructs x = hi + lo.
// ---------------------------------------------------------------------------
__global__ __launch_bounds__(128)
void ln_kernel(const float* __restrict__ in,
               __half* __restrict__ xh, __half* __restrict__ xl,
               const float* __restrict__ g, const float* __restrict__ bvec, int add)
{
    const int tid = threadIdx.x;
    const size_t row = blockIdx.x;
    float4 v = ((const float4*)(in + row * CO))[tid];
    float s  = v.x + v.y + v.z + v.w;
    float s2 = v.x * v.x + v.y * v.y + v.z * v.z + v.w * v.w;
    s  = warp_sum(s);
    s2 = warp_sum(s2);
    __shared__ float r1[4], r2[4];
    const int lane = tid & 31, warp = tid >> 5;
    if (lane == 0) { r1[warp] = s; r2[warp] = s2; }
    __syncthreads();
    float ss = r1[0] + r1[1] + r1[2] + r1[3];
    float sq = r2[0] + r2[1] + r2[2] + r2[3];
    float mu  = ss / CO;
    float var = sq / CO - mu * mu;
    float rs  = rsqrtf(var + EPSF);
    float4 g4 = ((const float4*)g)[tid];
    float4 b4 = ((const float4*)bvec)[tid];
    float4 f;
    f.x = (v.x - mu) * rs * g4.x + b4.x;
    f.y = (v.y - mu) * rs * g4.y + b4.y;
    f.z = (v.z - mu) * rs * g4.z + b4.z;
    f.w = (v.w - mu) * rs * g4.w + b4.w;
    uint2* ph = (uint2*)(xh + row * CO);
    uint2* pl = (uint2*)(xl + row * CO);
    if (add) {
        float4 o = join4f(ph[tid], pl[tid]);
        f.x += o.x; f.y += o.y; f.z += o.z; f.w += o.w;
    }
    uint2 H, L; split4f(f, H, L);
    ph[tid] = H;
    pl[tid] = L;
}

// ---------------------------------------------------------------------------
// Fused FINAL LayerNorm + residual + transpose to NCHW fp32 output.
// ---------------------------------------------------------------------------
__global__ __launch_bounds__(256)
void ln_tr_kernel(const float* __restrict__ in,
                  const __half* __restrict__ xh, const __half* __restrict__ xl,
                  const float* __restrict__ g, const float* __restrict__ bvec,
                  float* __restrict__ out)
{
    __shared__ float smu[32], srs[32], tile[32][33];
    const int b  = blockIdx.z;
    const int t0 = blockIdx.x * 32;
    const int tid = threadIdx.x;
    const int lane = tid & 31, warp = tid >> 5;

    // Phase A: stats for 32 rows, warp w handles rows 4w..4w+3
#pragma unroll
    for (int rr = 0; rr < 4; ++rr) {
        int r = warp * 4 + rr;
        const float4* row = (const float4*)(in + ((size_t)b * TT + t0 + r) * CO);
        float s = 0.f, s2 = 0.f;
#pragma unroll
        for (int i = 0; i < 4; ++i) {
            float4 v = row[lane + 32 * i];
            s  += v.x + v.y + v.z + v.w;
            s2 += v.x * v.x + v.y * v.y + v.z * v.z + v.w * v.w;
        }
        s = warp_sum(s); s2 = warp_sum(s2);
        if (lane == 0) {
            float mu = s / CO, var = s2 / CO - mu * mu;
            smu[r] = mu; srs[r] = rsqrtf(var + EPSF);
        }
    }
    __syncthreads();

    // Phase B: 16 f-tiles of 32
    const int tx = tid & 31, ty = tid >> 5;   // 32 x 8
    for (int f0 = 0; f0 < CO; f0 += 32) {
        float gg = g[f0 + tx], bb = bvec[f0 + tx];
#pragma unroll
        for (int j = 0; j < 32; j += 8) {
            int r = ty + j;
            size_t o = ((size_t)b * TT + t0 + r) * CO + f0 + tx;
            float xo = __half2float(xh[o]) + __half2float(xl[o]);
            tile[r][tx] = xo + (in[o] - smu[r]) * srs[r] * gg + bb;
        }
        __syncthreads();
#pragma unroll
        for (int j = 0; j < 32; j += 8)
            out[((size_t)b * CO + f0 + ty + j) * TT + t0 + tx] = tile[tx][ty + j];
        __syncthreads();
    }
}

// ---------------------------------------------------------------------------
// Attention core: 2 rows per 128-thread block, 64 threads/row, 4 ch/thread.
// ---------------------------------------------------------------------------
__global__ __launch_bounds__(128)
void att2_kernel(const float* __restrict__ qk,
                 const __half* __restrict__ xph, const __half* __restrict__ xpl,
                 __half* __restrict__ yh, __half* __restrict__ yl)
{
    const int tid = threadIdx.x;
    const int rid = tid >> 6, lt = tid & 63;
    const int row = blockIdx.x * 2 + rid;       // b*T + t
    const int b = row >> 12;
    const int t = row & (TT - 1);
    const int ho = t >> 6, wo = t & 63;
    const int pix0 = (ho << 1) * WW + (wo << 1);
    const size_t base = ((size_t)b * HWP + pix0) * CIN + 4 * lt;

    const float4 q4 = ((const float4*)(qk + (size_t)row * 256))[lt];

    float xv[4][4];
    const size_t offs[4] = {0, CIN, (size_t)WW * CIN, (size_t)WW * CIN + CIN};
#pragma unroll
    for (int w = 0; w < 4; ++w) {
        uint2 H = *(const uint2*)(xph + base + offs[w]);
        uint2 L = *(const uint2*)(xpl + base + offs[w]);
        float4 f = join4f(H, L);
        xv[w][0] = f.x; xv[w][1] = f.y; xv[w][2] = f.z; xv[w][3] = f.w;
    }
    float d[4];
#pragma unroll
    for (int w = 0; w < 4; ++w) {
        d[w] = q4.x * xv[w][0] + q4.y * xv[w][1] + q4.z * xv[w][2] + q4.w * xv[w][3];
        d[w] = warp_sum(d[w]);
    }
    __shared__ float red[2][4][2];
    const int lane = tid & 31, wp = (tid >> 5) & 1;
    if (lane == 0) {
        red[rid][0][wp] = d[0]; red[rid][1][wp] = d[1];
        red[rid][2][wp] = d[2]; red[rid][3][wp] = d[3];
    }
    __syncthreads();
    float a0 = red[rid][0][0] + red[rid][0][1];
    float a1 = red[rid][1][0] + red[rid][1][1];
    float a2 = red[rid][2][0] + red[rid][2][1];
    float a3 = red[rid][3][0] + red[rid][3][1];
    float mx = fmaxf(fmaxf(a0, a1), fmaxf(a2, a3));
    float e0 = __expf(a0 - mx), e1 = __expf(a1 - mx);
    float e2 = __expf(a2 - mx), e3 = __expf(a3 - mx);
    float inv = 1.f / (e0 + e1 + e2 + e3);
    e0 *= inv; e1 *= inv; e2 *= inv; e3 *= inv;

    float4 yv;
    yv.x = e0 * xv[0][0] + e1 * xv[1][0] + e2 * xv[2][0] + e3 * xv[3][0];
    yv.y = e0 * xv[0][1] + e1 * xv[1][1] + e2 * xv[2][1] + e3 * xv[3][1];
    yv.z = e0 * xv[0][2] + e1 * xv[1][2] + e2 * xv[2][2] + e3 * xv[3][2];
    yv.w = e0 * xv[0][3] + e1 * xv[1][3] + e2 * xv[2][3] + e3 * xv[3][3];
    uint2 H, L; split4f(yv, H, L);
    *(uint2*)(yh + (size_t)row * 256 + 4 * lt) = H;
    *(uint2*)(yl + (size_t)row * 256 + 4 * lt) = L;
}

// ---------------------------------------------------------------------------
extern "C" void kernel_launch(void* const* d_in, const int* in_sizes, int n_in,
                              void* d_out, int out_size)
{
    const float* x_in   = (const float*)d_in[0];
    const float* conv_w = (const float*)d_in[1];
    const float* conv_b = (const float*)d_in[2];
    const float* k_w    = (const float*)d_in[3];
    const float* k_b    = (const float*)d_in[4];   // const over window -> drops in softmax
    const float* q_w    = (const float*)d_in[5];
    const float* q_b    = (const float*)d_in[6];
    const float* v_w    = (const float*)d_in[7];
    const float* v_b    = (const float*)d_in[8];
    const float* mlp_w  = (const float*)d_in[9];
    const float* mlp_b  = (const float*)d_in[10];
    const float* lnc_g  = (const float*)d_in[11];
    const float* lnc_b  = (const float*)d_in[12];
    const float* lnv_g  = (const float*)d_in[13];
    const float* lnv_b  = (const float*)d_in[14];
    const float* lnm_g  = (const float*)d_in[15];
    const float* lnm_b  = (const float*)d_in[16];
    float* out = (float*)d_out;
    (void)k_b;

    float *pq, *cvec;
    __half *xph, *xpl, *xh, *xl, *yh, *yl, *wh, *wl, *w2h, *w2l;
    cudaGetSymbolAddress((void**)&pq, g_q);
    cudaGetSymbolAddress((void**)&xph, g_xph);
    cudaGetSymbolAddress((void**)&xpl, g_xpl);
    cudaGetSymbolAddress((void**)&xh, g_xh);
    cudaGetSymbolAddress((void**)&xl, g_xl);
    cudaGetSymbolAddress((void**)&yh, g_yh);
    cudaGetSymbolAddress((void**)&yl, g_yl);
    cudaGetSymbolAddress((void**)&wh, g_wh);
    cudaGetSymbolAddress((void**)&wl, g_wl);
    cudaGetSymbolAddress((void**)&w2h, g_w2h);
    cudaGetSymbolAddress((void**)&w2l, g_w2l);
    cudaGetSymbolAddress((void**)&cvec, g_cvec);

    cudaFuncSetAttribute((const void*)hgemm_conv, cudaFuncAttributeMaxDynamicSharedMemorySize, SMEMDYN);
    cudaFuncSetAttribute((const void*)hgemm<16>,  cudaFuncAttributeMaxDynamicSharedMemorySize, SMEMDYN);
    cudaFuncSetAttribute((const void*)hgemm<8>,   cudaFuncAttributeMaxDynamicSharedMemorySize, SMEMDYN);

    // 1) split weights  2) split+transpose input  3) W2 = K_w^T Q_w (+ c)
    split_w3<<<(W_TOTAL + 255) / 256, 256>>>(conv_w, v_w, mlp_w);
    split_xp<<<dim3(HWP / 32, CIN / 64, NB), 256>>>(x_in);
    w2_kernel<<<dim3(8, 16), 256>>>(k_w, q_w, q_b);

    // 4) patchify conv (direct pixel-major gather) -> staging, 5) LN -> x_out
    hgemm_conv<<<dim3(TT / 128, 4, NB), 256, SMEMDYN>>>(
        xph, xpl, wh + OFF_CONV, wl + OFF_CONV, conv_b, pq);
    ln_kernel<<<NB * TT, 128>>>(pq, xh, xl, lnc_g, lnc_b, 0);

    // 6+) iterative grouping (launch #6 = qk GEMM for ncu -s 5 -c 1)
    for (int it = 0; it < ITERS; it++) {
        // qk[t] = W2 x_out[t] + c   (M=TT, N=256, K=512)
        hgemm<16><<<dim3(TT / 128, 2, NB), 256, SMEMDYN>>>(
            xh, xl, w2h, w2l, cvec, pq, TT, 256);
        // att: softmax(x_in·qk) over 2x2 window, y = Σ att·x_in
        att2_kernel<<<NB * TT / 2, 128>>>(pq, xph, xpl, yh, yl);
        // upd = V_w y + v_b   (M=TT, N=512, K=256)
        hgemm<8><<<dim3(TT / 128, 4, NB), 256, SMEMDYN>>>(
            yh, yl, wh + OFF_V, wl + OFF_V, v_b, pq, TT, CO);
        // x += LN(upd)
        ln_kernel<<<NB * TT, 128>>>(pq, xh, xl, lnv_g, lnv_b, 1);
        // mlp = M_w x + mlp_b ; x += LN(mlp)
        hgemm<16><<<dim3(TT / 128, 4, NB), 256, SMEMDYN>>>(
            xh, xl, wh + OFF_MLP, wl + OFF_MLP, mlp_b, pq, TT, CO);
        if (it < ITERS - 1) {
            ln_kernel<<<NB * TT, 128>>>(pq, xh, xl, lnm_g, lnm_b, 1);
        } else {
            // final: fused LN + residual + transpose to NCHW output
            ln_tr_kernel<<<dim3(TT / 32, 1, NB), 256>>>(pq, xh, xl, lnm_g, lnm_b, out);
        }
    }
}

// round 16
// speedup vs baseline: 1.0177x; 1.0177x over previous
#include <cuda_runtime.h>
#include <cuda_fp16.h>
#include <cstdint>

// Problem constants
#define NB   4
#define CIN  256
#define HH   128
#define WW   128
#define HWP  (HH*WW)      // 16384
#define CO   512
#define TT   4096         // 64*64 output pixels
#define EPSF 1e-5f
#define ITERS 3

// ---------------------------------------------------------------------------
// Scratch
// ---------------------------------------------------------------------------
__device__ float g_q[(size_t)NB*TT*CO];    // staging: conv/qk/upd/mlp outputs

// fp16 split operands (x_out lives ONLY as hi/lo pair; x = hi + lo to ~2^-24)
__device__ __align__(16) __half g_xph[(size_t)NB*HWP*CIN];  // x_in hi, pixel-major [b][pix][c]
__device__ __align__(16) __half g_xpl[(size_t)NB*HWP*CIN];  // x_in lo
__device__ __align__(16) __half g_xh[(size_t)NB*TT*CO];     // x_out hi, M-major [b][t][c]
__device__ __align__(16) __half g_xl[(size_t)NB*TT*CO];     // x_out lo
__device__ __align__(16) __half g_yh[(size_t)NB*TT*CIN];    // y hi, [b][t][j]
__device__ __align__(16) __half g_yl[(size_t)NB*TT*CIN];    // y lo
// weights: conv (reordered [n][w*256+c]) | v | mlp  ([n][k] row-major)
#define OFF_CONV 0
#define OFF_V    (512*1024)
#define OFF_MLP  (OFF_V + 512*256)
#define W_TOTAL  (OFF_MLP + 512*512)
__device__ __align__(16) __half g_wh[W_TOTAL];
__device__ __align__(16) __half g_wl[W_TOTAL];
// W2 = K_w^T Q_w (256 x 512) split, + c = K_w^T q_b
__device__ __align__(16) __half g_w2h[256*512];
__device__ __align__(16) __half g_w2l[256*512];
__device__ float g_cvec[256];

// ===========================================================================
// helpers
// ===========================================================================
__device__ __forceinline__ uint32_t smem_to_u32(const void* p) {
    uint32_t a;
    asm("{ .reg .u64 t; cvta.to.shared.u64 t, %1; cvt.u32.u64 %0, t; }"
        : "=r"(a) : "l"(p));
    return a;
}
__device__ __forceinline__ float warp_sum(float v) {
#pragma unroll
    for (int o = 16; o > 0; o >>= 1) v += __shfl_xor_sync(0xffffffffu, v, o);
    return v;
}
__device__ __forceinline__ void mma16816(float* c, const uint32_t* a, const uint32_t* b) {
    asm("mma.sync.aligned.m16n8k16.row.col.f32.f16.f16.f32 "
        "{%0,%1,%2,%3}, {%4,%5,%6,%7}, {%8,%9}, {%0,%1,%2,%3};"
        : "+f"(c[0]), "+f"(c[1]), "+f"(c[2]), "+f"(c[3])
        : "r"(a[0]), "r"(a[1]), "r"(a[2]), "r"(a[3]), "r"(b[0]), "r"(b[1]));
}
__device__ __forceinline__ void ldsm4(uint32_t* r, uint32_t a) {
    asm("ldmatrix.sync.aligned.m8n8.x4.shared.b16 {%0,%1,%2,%3}, [%4];"
        : "=r"(r[0]), "=r"(r[1]), "=r"(r[2]), "=r"(r[3]) : "r"(a) : "memory");
}
__device__ __forceinline__ void cp16(uint32_t sm, const void* g) {
    asm volatile("cp.async.cg.shared.global [%0], [%1], 16;"
        :: "r"(sm), "l"(g) : "memory");
}
__device__ __forceinline__ void cp_commit() {
    asm volatile("cp.async.commit_group;" ::: "memory");
}
template<int N> __device__ __forceinline__ void cp_wait() {
    asm volatile("cp.async.wait_group %0;" :: "n"(N) : "memory");
}
__device__ __forceinline__ void split1f(float x, __half& h, __half& l) {
    h = __float2half_rn(x);
    l = __float2half_rn(x - __half2float(h));
}
__device__ __forceinline__ void split4f(float4 f, uint2& H, uint2& L) {
    __half h[4], l[4];
    split1f(f.x, h[0], l[0]); split1f(f.y, h[1], l[1]);
    split1f(f.z, h[2], l[2]); split1f(f.w, h[3], l[3]);
    __half2 h0 = __halves2half2(h[0], h[1]), h1 = __halves2half2(h[2], h[3]);
    __half2 l0 = __halves2half2(l[0], l[1]), l1 = __halves2half2(l[2], l[3]);
    H.x = *(uint32_t*)&h0; H.y = *(uint32_t*)&h1;
    L.x = *(uint32_t*)&l0; L.y = *(uint32_t*)&l1;
}
__device__ __forceinline__ float4 join4f(uint2 H, uint2 L) {
    __half2 h0 = *(__half2*)&H.x, h1 = *(__half2*)&H.y;
    __half2 l0 = *(__half2*)&L.x, l1 = *(__half2*)&L.y;
    float4 f;
    f.x = __half2float(__low2half(h0))  + __half2float(__low2half(l0));
    f.y = __half2float(__high2half(h0)) + __half2float(__high2half(l0));
    f.z = __half2float(__low2half(h1))  + __half2float(__low2half(l1));
    f.w = __half2float(__high2half(h1)) + __half2float(__high2half(l1));
    return f;
}

// ===========================================================================
// setup kernels
// ===========================================================================
// conv region reordered: W[n][w*256+c] = conv_w[n][c*4+w]
__global__ __launch_bounds__(256)
void split_w3(const float* __restrict__ w0, const float* __restrict__ w1,
              const float* __restrict__ w2)
{
    int i = blockIdx.x * 256 + threadIdx.x;
    if (i >= W_TOTAL) return;
    const float* s; int off;
    if (i < OFF_V) {
        int n = i >> 10, k = i & 1023;
        int w = k >> 8, cc = k & 255;
        s = w0; off = n * 1024 + cc * 4 + w;
    }
    else if (i < OFF_MLP) { s = w1; off = i - OFF_V; }
    else                  { s = w2; off = i - OFF_MLP; }
    __half h, l; split1f(s[off], h, l);
    g_wh[i] = h; g_wl[i] = l;
}

// x_in (NCHW) -> pixel-major fp16 hi/lo, one pass.
__global__ __launch_bounds__(256)
void split_xp(const float* __restrict__ x)
{
    __shared__ float sm[64][33];
    const int p0 = blockIdx.x * 32;
    const int c0 = blockIdx.y * 64;
    const int b  = blockIdx.z;
    const float* xb = x + ((size_t)b * CIN + c0) * HWP + p0;
    const int tx = threadIdx.x & 31, ty = threadIdx.x >> 5;   // 32 x 8
#pragma unroll
    for (int cc = ty; cc < 64; cc += 8)
        sm[cc][tx] = xb[(size_t)cc * HWP + tx];
    __syncthreads();
    const int cp = tx, pg = ty;
#pragma unroll
    for (int p = pg; p < 32; p += 8) {
        float f0 = sm[2 * cp][p], f1 = sm[2 * cp + 1][p];
        __half h0, l0, h1, l1; split1f(f0, h0, l0); split1f(f1, h1, l1);
        __half2 H = __halves2half2(h0, h1), L = __halves2half2(l0, l1);
        size_t o = ((size_t)b * HWP + p0 + p) * CIN + c0;
        ((uint32_t*)(g_xph + o))[cp] = *(uint32_t*)&H;
        ((uint32_t*)(g_xpl + o))[cp] = *(uint32_t*)&L;
    }
}

// W2[j][f] = sum_o K_w[o][j] * Q_w[o][f], split to fp16 hi/lo; c = K_w^T q_b.
__global__ __launch_bounds__(256)
void w2_kernel(const float* __restrict__ Kw, const float* __restrict__ Qw,
               const float* __restrict__ qb)
{
    __shared__ float Ks[32][33], Qs[32][33];
    const int j0 = blockIdx.x * 32, f0 = blockIdx.y * 32;
    const int txx = threadIdx.x & 15, tyy = threadIdx.x >> 4;
    float acc[2][2] = {{0.f, 0.f}, {0.f, 0.f}};
    for (int o0 = 0; o0 < 512; o0 += 32) {
#pragma unroll
        for (int l = threadIdx.x; l < 1024; l += 256) {
            int oo = l >> 5, jj = l & 31;
            Ks[oo][jj] = Kw[(size_t)(o0 + oo) * 256 + j0 + jj];
            Qs[oo][jj] = Qw[(size_t)(o0 + oo) * 512 + f0 + jj];
        }
        __syncthreads();
#pragma unroll
        for (int oo = 0; oo < 32; ++oo) {
            float k0 = Ks[oo][tyy * 2], k1 = Ks[oo][tyy * 2 + 1];
            float q0 = Qs[oo][txx * 2], q1 = Qs[oo][txx * 2 + 1];
            acc[0][0] += k0 * q0; acc[0][1] += k0 * q1;
            acc[1][0] += k1 * q0; acc[1][1] += k1 * q1;
        }
        __syncthreads();
    }
#pragma unroll
    for (int a = 0; a < 2; a++)
#pragma unroll
        for (int bb = 0; bb < 2; bb++) {
            int j = j0 + tyy * 2 + a, f = f0 + txx * 2 + bb;
            __half h, l; split1f(acc[a][bb], h, l);
            g_w2h[(size_t)j * 512 + f] = h;
            g_w2l[(size_t)j * 512 + f] = l;
        }
    if (blockIdx.y == 0 && threadIdx.x < 32) {
        int j = j0 + threadIdx.x;
        float s = 0.f;
        for (int o = 0; o < 512; ++o) s += Kw[(size_t)o * 256 + j] * qb[o];
        g_cvec[j] = s;
    }
}

// ===========================================================================
// HMMA split-fp16 GEMM core (tile 128x128, K-chunk 32, 8 warps 2x4,
// warp tile 64x32, 3-stage cp.async, ks-split with mid-chunk issue).
// Two compute variants (measured per-kernel):
//   gemm_compute_ks     — all A frags up-front (best for M-major hgemm, R13)
//   gemm_compute_ks_mt  — mt-pipelined hh sweep (best for conv, R14/R15)
// ===========================================================================
#define STAGE   32768
#define SMEMDYN (3*STAGE)

// M-major A loader + B loader (q/mlp/qk/upd GEMMs)
template<int K>
__device__ __forceinline__ void gemm_issue(
    uint32_t sb, int s, int c, int tid, int m0, int n0,
    const __half* pAh, const __half* pAl,
    const __half* Bh, const __half* Bl)
{
    const int k0 = c * 32;
    const uint32_t As = sb + s * STAGE;
    const uint32_t Bs = As + 16384;
#pragma unroll
    for (int j = 0; j < 4; j++) {
        int idx = tid + j * 256;
        int r = idx >> 3, q = idx & 7;
        uint32_t sm = As + r * 128 + ((q ^ (r & 7)) << 4);
        const __half* g = ((q < 4) ? pAh : pAl)
                          + (size_t)(m0 + r) * K + k0 + (q & 3) * 8;
        cp16(sm, g);
    }
#pragma unroll
    for (int j = 0; j < 4; j++) {
        int idx = tid + j * 256;
        int r = idx >> 3, q = idx & 7;
        uint32_t sm = Bs + r * 128 + ((q ^ (r & 7)) << 4);
        const __half* g = ((q < 4) ? Bh : Bl)
                          + (size_t)(n0 + r) * K + k0 + (q & 3) * 8;
        cp16(sm, g);
    }
    cp_commit();
}

// conv A loader: A[t][k], k = w*256 + cch; reads pixel-major xph/xpl directly.
__device__ __forceinline__ void gemm_issue_conv(
    uint32_t sb, int s, int c, int tid,
    const size_t* pbase,               // [4] per-j row base offsets (halves)
    const __half* xph, const __half* xpl,
    const __half* Bh, const __half* Bl, int n0)
{
    const int k0 = c * 32;
    const int w = c >> 3;              // window pixel index 0..3
    const size_t woff = (size_t)(w >> 1) * ((size_t)WW * CIN)
                      + (size_t)(w & 1) * CIN;
    const int cb = (c & 7) * 32;       // channel base within pixel
    const uint32_t As = sb + s * STAGE;
    const uint32_t Bs = As + 16384;
#pragma unroll
    for (int j = 0; j < 4; j++) {
        int idx = tid + j * 256;
        int r = idx >> 3, q = idx & 7;   // r = (tid>>3) + 32j, q = tid&7
        uint32_t sm = As + r * 128 + ((q ^ (r & 7)) << 4);
        const __half* g = ((q < 4) ? xph : xpl)
                          + pbase[j] + woff + cb + (q & 3) * 8;
        cp16(sm, g);
    }
#pragma unroll
    for (int j = 0; j < 4; j++) {
        int idx = tid + j * 256;
        int r = idx >> 3, q = idx & 7;
        uint32_t sm = Bs + r * 128 + ((q ^ (r & 7)) << 4);
        const __half* g = ((q < 4) ? Bh : Bl)
                          + (size_t)(n0 + r) * 1024 + k0 + (q & 3) * 8;
        cp16(sm, g);
    }
    cp_commit();
}

// R13 form: all A fragments loaded up-front after B.
template<int KS>
__device__ __forceinline__ void gemm_compute_ks(
    uint32_t sb, int s, int lane, int wm, int wn, float acc[4][4][4])
{
    const uint32_t As = sb + s * STAGE;
    const uint32_t Bs = As + 16384;
    const int g = lane >> 3;
    const uint32_t l7 = lane & 7;
    uint32_t bh[8], bl[8], ah[16], al[16];
    {
        uint32_t nrow = wn * 32 + (g >> 1) * 8 + l7;
        uint32_t cH = ((KS * 2 + (g & 1)) ^ l7) << 4;
        uint32_t cL = ((KS * 2 + (g & 1) + 4) ^ l7) << 4;
        uint32_t r0 = Bs + nrow * 128;
        ldsm4(&bh[0], r0 + cH);
        ldsm4(&bl[0], r0 + cL);
        uint32_t r1 = r0 + 16 * 128;
        ldsm4(&bh[4], r1 + cH);
        ldsm4(&bl[4], r1 + cL);
    }
#pragma unroll
    for (int mt = 0; mt < 4; ++mt) {
        uint32_t mrow = wm * 64 + mt * 16 + (g & 1) * 8 + l7;
        uint32_t ch = KS * 2 + (g >> 1);
        uint32_t ra = As + mrow * 128;
        ldsm4(&ah[mt * 4], ra + ((ch ^ l7) << 4));
        ldsm4(&al[mt * 4], ra + (((ch + 4) ^ l7) << 4));
    }
#pragma unroll
    for (int mt = 0; mt < 4; ++mt)
#pragma unroll
        for (int nt = 0; nt < 4; ++nt) mma16816(acc[mt][nt], &ah[mt * 4], &bh[nt * 2]);
#pragma unroll
    for (int mt = 0; mt < 4; ++mt)
#pragma unroll
        for (int nt = 0; nt < 4; ++nt) mma16816(acc[mt][nt], &ah[mt * 4], &bl[nt * 2]);
#pragma unroll
    for (int mt = 0; mt < 4; ++mt)
#pragma unroll
        for (int nt = 0; nt < 4; ++nt) mma16816(acc[mt][nt], &al[mt * 4], &bh[nt * 2]);
}

// mt-pipelined form (conv only; measured faster there).
template<int KS>
__device__ __forceinline__ void gemm_compute_ks_mt(
    uint32_t sb, int s, int lane, int wm, int wn, float acc[4][4][4])
{
    const uint32_t As = sb + s * STAGE;
    const uint32_t Bs = As + 16384;
    const int g = lane >> 3;
    const uint32_t l7 = lane & 7;
    uint32_t bh[8], bl[8], ah[16], al[16];
    {
        uint32_t nrow = wn * 32 + (g >> 1) * 8 + l7;
        uint32_t cH = ((KS * 2 + (g & 1)) ^ l7) << 4;
        uint32_t cL = ((KS * 2 + (g & 1) + 4) ^ l7) << 4;
        uint32_t r0 = Bs + nrow * 128;
        ldsm4(&bh[0], r0 + cH);
        ldsm4(&bl[0], r0 + cL);
        uint32_t r1 = r0 + 16 * 128;
        ldsm4(&bh[4], r1 + cH);
        ldsm4(&bl[4], r1 + cL);
    }
    const uint32_t ch = KS * 2 + (g >> 1);
    auto loadA = [&](int mt) {
        uint32_t mrow = wm * 64 + mt * 16 + (g & 1) * 8 + l7;
        uint32_t ra = As + mrow * 128;
        ldsm4(&ah[mt * 4], ra + ((ch ^ l7) << 4));
        ldsm4(&al[mt * 4], ra + (((ch + 4) ^ l7) << 4));
    };
    loadA(0);
#pragma unroll
    for (int mt = 0; mt < 4; ++mt) {
        if (mt < 3) loadA(mt + 1);
#pragma unroll
        for (int nt = 0; nt < 4; ++nt) mma16816(acc[mt][nt], &ah[mt * 4], &bh[nt * 2]);
    }
#pragma unroll
    for (int mt = 0; mt < 4; ++mt)
#pragma unroll
        for (int nt = 0; nt < 4; ++nt) mma16816(acc[mt][nt], &ah[mt * 4], &bl[nt * 2]);
#pragma unroll
    for (int mt = 0; mt < 4; ++mt)
#pragma unroll
        for (int nt = 0; nt < 4; ++nt) mma16816(acc[mt][nt], &al[mt * 4], &bh[nt * 2]);
}

__device__ __forceinline__ void gemm_epilogue(
    float acc[4][4][4], const float* bias, float* C,
    int lane, int wm, int wn, int m0, int n0, size_t bM, int ldc)
{
    const int gq = lane >> 2, tq = lane & 3;
#pragma unroll
    for (int mt = 0; mt < 4; ++mt) {
        int mrow = m0 + wm * 64 + mt * 16 + gq;
        float* Cr = C + (bM + mrow) * ldc + n0;
#pragma unroll
        for (int nt = 0; nt < 4; ++nt) {
            int col = wn * 32 + nt * 8 + tq * 2;
            float b0 = bias[n0 + col], b1 = bias[n0 + col + 1];
            float2 v0; v0.x = acc[mt][nt][0] + b0; v0.y = acc[mt][nt][1] + b1;
            *(float2*)&Cr[col] = v0;
            float2 v1; v1.x = acc[mt][nt][2] + b0; v1.y = acc[mt][nt][3] + b1;
            *(float2*)&Cr[col + 8 * ldc] = v1;
        }
    }
}

template<int NCH>
__global__ __launch_bounds__(256, 2)
void hgemm(const __half* __restrict__ Ah, const __half* __restrict__ Al,
           const __half* __restrict__ Bh, const __half* __restrict__ Bl,
           const float* __restrict__ bias, float* __restrict__ C,
           int M, int ldc)
{
    constexpr int K = NCH * 32;
    extern __shared__ char sm_[];
    const uint32_t sb = smem_to_u32(sm_);
    const int tid = threadIdx.x;
    const int lane = tid & 31;
    const int wid = tid >> 5;
    const int wm = wid & 1, wn = wid >> 1;
    const int m0 = blockIdx.x * 128, n0 = blockIdx.y * 128, bz = blockIdx.z;
    const __half* pAh = Ah + (size_t)bz * M * K;
    const __half* pAl = Al + (size_t)bz * M * K;

    float acc[4][4][4];
#pragma unroll
    for (int i = 0; i < 4; i++)
#pragma unroll
        for (int j = 0; j < 4; j++)
#pragma unroll
            for (int r = 0; r < 4; r++) acc[i][j][r] = 0.f;

    gemm_issue<K>(sb, 0, 0, tid, m0, n0, pAh, pAl, Bh, Bl);
    gemm_issue<K>(sb, 1, 1, tid, m0, n0, pAh, pAl, Bh, Bl);
#pragma unroll
    for (int c = 0; c < NCH; ++c) {
        if (c < NCH - 1) cp_wait<1>(); else cp_wait<0>();
        __syncthreads();
        gemm_compute_ks<0>(sb, c % 3, lane, wm, wn, acc);
        if (c + 2 < NCH) gemm_issue<K>(sb, (c + 2) % 3, c + 2, tid, m0, n0, pAh, pAl, Bh, Bl);
        gemm_compute_ks<1>(sb, c % 3, lane, wm, wn, acc);
    }
    gemm_epilogue(acc, bias, C, lane, wm, wn, m0, n0, (size_t)bz * M, ldc);
}

// conv GEMM: A gathered from pixel-major x_in (k = w*256 + c), K=1024.
__global__ __launch_bounds__(256, 2)
void hgemm_conv(const __half* __restrict__ xph, const __half* __restrict__ xpl,
                const __half* __restrict__ Bh, const __half* __restrict__ Bl,
                const float* __restrict__ bias, float* __restrict__ C)
{
    constexpr int NCH = 32;
    extern __shared__ char sm_[];
    const uint32_t sb = smem_to_u32(sm_);
    const int tid = threadIdx.x;
    const int lane = tid & 31;
    const int wid = tid >> 5;
    const int wm = wid & 1, wn = wid >> 1;
    const int m0 = blockIdx.x * 128, n0 = blockIdx.y * 128, bz = blockIdx.z;

    // per-j (4 A rows per thread: r = tid>>3 + 32j) top-left pixel bases
    size_t pbase[4];
    {
        int r0 = tid >> 3;
#pragma unroll
        for (int j = 0; j < 4; ++j) {
            int t = m0 + r0 + j * 32, ho = t >> 6, wo = t & 63;
            int pix = (ho << 1) * WW + (wo << 1);
            pbase[j] = ((size_t)bz * HWP + pix) * CIN;
        }
    }

    float acc[4][4][4];
#pragma unroll
    for (int i = 0; i < 4; i++)
#pragma unroll
        for (int j = 0; j < 4; j++)
#pragma unroll
            for (int r = 0; r < 4; r++) acc[i][j][r] = 0.f;

    gemm_issue_conv(sb, 0, 0, tid, pbase, xph, xpl, Bh, Bl, n0);
    gemm_issue_conv(sb, 1, 1, tid, pbase, xph, xpl, Bh, Bl, n0);
#pragma unroll
    for (int c = 0; c < NCH; ++c) {
        if (c < NCH - 1) cp_wait<1>(); else cp_wait<0>();
        __syncthreads();
        gemm_compute_ks_mt<0>(sb, c % 3, lane, wm, wn, acc);
        if (c + 2 < NCH) gemm_issue_conv(sb, (c + 2) % 3, c + 2, tid, pbase, xph, xpl, Bh, Bl, n0);
        gemm_compute_ks_mt<1>(sb, c % 3, lane, wm, wn, acc);
    }
    gemm_epilogue(acc, bias, C, lane, wm, wn, m0, n0, (size_t)bz * TT, CO);
}

// ---------------------------------------------------------------------------
// Channel LayerNorm over CO=512, float4-vectorized, 128 threads/row (R13 form).
// x_out lives as fp16 hi/lo pair; add-path reconstructs x = hi + lo.
// ---------------------------------------------------------------------------
__global__ __launch_bounds__(128)
void ln_kernel(const float* __restrict__ in,
               __half* __restrict__ xh, __half* __restrict__ xl,
               const float* __restrict__ g, const float* __restrict__ bvec, int add)
{
    const int tid = threadIdx.x;
    const size_t row = blockIdx.x;
    float4 v = ((const float4*)(in + row * CO))[tid];
    float s  = v.x + v.y + v.z + v.w;
    float s2 = v.x * v.x + v.y * v.y + v.z * v.z + v.w * v.w;
    s  = warp_sum(s);
    s2 = warp_sum(s2);
    __shared__ float r1[4], r2[4];
    const int lane = tid & 31, warp = tid >> 5;
    if (lane == 0) { r1[warp] = s; r2[warp] = s2; }
    __syncthreads();
    float ss = r1[0] + r1[1] + r1[2] + r1[3];
    float sq = r2[0] + r2[1] + r2[2] + r2[3];
    float mu  = ss / CO;
    float var = sq / CO - mu * mu;
    float rs  = rsqrtf(var + EPSF);
    float4 g4 = ((const float4*)g)[tid];
    float4 b4 = ((const float4*)bvec)[tid];
    float4 f;
    f.x = (v.x - mu) * rs * g4.x + b4.x;
    f.y = (v.y - mu) * rs * g4.y + b4.y;
    f.z = (v.z - mu) * rs * g4.z + b4.z;
    f.w = (v.w - mu) * rs * g4.w + b4.w;
    uint2* ph = (uint2*)(xh + row * CO);
    uint2* pl = (uint2*)(xl + row * CO);
    if (add) {
        float4 o = join4f(ph[tid], pl[tid]);
        f.x += o.x; f.y += o.y; f.z += o.z; f.w += o.w;
    }
    uint2 H, L; split4f(f, H, L);
    ph[tid] = H;
    pl[tid] = L;
}

// ---------------------------------------------------------------------------
// Fused FINAL LayerNorm + residual + transpose to NCHW fp32 output.
// ---------------------------------------------------------------------------
__global__ __launch_bounds__(256)
void ln_tr_kernel(const float* __restrict__ in,
                  const __half* __restrict__ xh, const __half* __restrict__ xl,
                  const float* __restrict__ g, const float* __restrict__ bvec,
                  float* __restrict__ out)
{
    __shared__ float smu[32], srs[32], tile[32][33];
    const int b  = blockIdx.z;
    const int t0 = blockIdx.x * 32;
    const int tid = threadIdx.x;
    const int lane = tid & 31, warp = tid >> 5;

    // Phase A: stats for 32 rows, warp w handles rows 4w..4w+3
#pragma unroll
    for (int rr = 0; rr < 4; ++rr) {
        int r = warp * 4 + rr;
        const float4* row = (const float4*)(in + ((size_t)b * TT + t0 + r) * CO);
        float s = 0.f, s2 = 0.f;
#pragma unroll
        for (int i = 0; i < 4; ++i) {
            float4 v = row[lane + 32 * i];
            s  += v.x + v.y + v.z + v.w;
            s2 += v.x * v.x + v.y * v.y + v.z * v.z + v.w * v.w;
        }
        s = warp_sum(s); s2 = warp_sum(s2);
        if (lane == 0) {
            float mu = s / CO, var = s2 / CO - mu * mu;
            smu[r] = mu; srs[r] = rsqrtf(var + EPSF);
        }
    }
    __syncthreads();

    // Phase B: 16 f-tiles of 32
    const int tx = tid & 31, ty = tid >> 5;   // 32 x 8
    for (int f0 = 0; f0 < CO; f0 += 32) {
        float gg = g[f0 + tx], bb = bvec[f0 + tx];
#pragma unroll
        for (int j = 0; j < 32; j += 8) {
            int r = ty + j;
            size_t o = ((size_t)b * TT + t0 + r) * CO + f0 + tx;
            float xo = __half2float(xh[o]) + __half2float(xl[o]);
            tile[r][tx] = xo + (in[o] - smu[r]) * srs[r] * gg + bb;
        }
        __syncthreads();
#pragma unroll
        for (int j = 0; j < 32; j += 8)
            out[((size_t)b * CO + f0 + ty + j) * TT + t0 + tx] = tile[tx][ty + j];
        __syncthreads();
    }
}

// ---------------------------------------------------------------------------
// Attention core: 2 rows per 128-thread block, 64 threads/row, 4 ch/thread.
// ---------------------------------------------------------------------------
__global__ __launch_bounds__(128)
void att2_kernel(const float* __restrict__ qk,
                 const __half* __restrict__ xph, const __half* __restrict__ xpl,
                 __half* __restrict__ yh, __half* __restrict__ yl)
{
    const int tid = threadIdx.x;
    const int rid = tid >> 6, lt = tid & 63;
    const int row = blockIdx.x * 2 + rid;       // b*T + t
    const int b = row >> 12;
    const int t = row & (TT - 1);
    const int ho = t >> 6, wo = t & 63;
    const int pix0 = (ho << 1) * WW + (wo << 1);
    const size_t base = ((size_t)b * HWP + pix0) * CIN + 4 * lt;

    const float4 q4 = ((const float4*)(qk + (size_t)row * 256))[lt];

    float xv[4][4];
    const size_t offs[4] = {0, CIN, (size_t)WW * CIN, (size_t)WW * CIN + CIN};
#pragma unroll
    for (int w = 0; w < 4; ++w) {
        uint2 H = *(const uint2*)(xph + base + offs[w]);
        uint2 L = *(const uint2*)(xpl + base + offs[w]);
        float4 f = join4f(H, L);
        xv[w][0] = f.x; xv[w][1] = f.y; xv[w][2] = f.z; xv[w][3] = f.w;
    }
    float d[4];
#pragma unroll
    for (int w = 0; w < 4; ++w) {
        d[w] = q4.x * xv[w][0] + q4.y * xv[w][1] + q4.z * xv[w][2] + q4.w * xv[w][3];
        d[w] = warp_sum(d[w]);
    }
    __shared__ float red[2][4][2];
    const int lane = tid & 31, wp = (tid >> 5) & 1;
    if (lane == 0) {
        red[rid][0][wp] = d[0]; red[rid][1][wp] = d[1];
        red[rid][2][wp] = d[2]; red[rid][3][wp] = d[3];
    }
    __syncthreads();
    float a0 = red[rid][0][0] + red[rid][0][1];
    float a1 = red[rid][1][0] + red[rid][1][1];
    float a2 = red[rid][2][0] + red[rid][2][1];
    float a3 = red[rid][3][0] + red[rid][3][1];
    float mx = fmaxf(fmaxf(a0, a1), fmaxf(a2, a3));
    float e0 = __expf(a0 - mx), e1 = __expf(a1 - mx);
    float e2 = __expf(a2 - mx), e3 = __expf(a3 - mx);
    float inv = 1.f / (e0 + e1 + e2 + e3);
    e0 *= inv; e1 *= inv; e2 *= inv; e3 *= inv;

    float4 yv;
    yv.x = e0 * xv[0][0] + e1 * xv[1][0] + e2 * xv[2][0] + e3 * xv[3][0];
    yv.y = e0 * xv[0][1] + e1 * xv[1][1] + e2 * xv[2][1] + e3 * xv[3][1];
    yv.z = e0 * xv[0][2] + e1 * xv[1][2] + e2 * xv[2][2] + e3 * xv[3][2];
    yv.w = e0 * xv[0][3] + e1 * xv[1][3] + e2 * xv[2][3] + e3 * xv[3][3];
    uint2 H, L; split4f(yv, H, L);
    *(uint2*)(yh + (size_t)row * 256 + 4 * lt) = H;
    *(uint2*)(yl + (size_t)row * 256 + 4 * lt) = L;
}

// ---------------------------------------------------------------------------
extern "C" void kernel_launch(void* const* d_in, const int* in_sizes, int n_in,
                              void* d_out, int out_size)
{
    const float* x_in   = (const float*)d_in[0];
    const float* conv_w = (const float*)d_in[1];
    const float* conv_b = (const float*)d_in[2];
    const float* k_w    = (const float*)d_in[3];
    const float* k_b    = (const float*)d_in[4];   // const over window -> drops in softmax
    const float* q_w    = (const float*)d_in[5];
    const float* q_b    = (const float*)d_in[6];
    const float* v_w    = (const float*)d_in[7];
    const float* v_b    = (const float*)d_in[8];
    const float* mlp_w  = (const float*)d_in[9];
    const float* mlp_b  = (const float*)d_in[10];
    const float* lnc_g  = (const float*)d_in[11];
    const float* lnc_b  = (const float*)d_in[12];
    const float* lnv_g  = (const float*)d_in[13];
    const float* lnv_b  = (const float*)d_in[14];
    const float* lnm_g  = (const float*)d_in[15];
    const float* lnm_b  = (const float*)d_in[16];
    float* out = (float*)d_out;
    (void)k_b;

    float *pq, *cvec;
    __half *xph, *xpl, *xh, *xl, *yh, *yl, *wh, *wl, *w2h, *w2l;
    cudaGetSymbolAddress((void**)&pq, g_q);
    cudaGetSymbolAddress((void**)&xph, g_xph);
    cudaGetSymbolAddress((void**)&xpl, g_xpl);
    cudaGetSymbolAddress((void**)&xh, g_xh);
    cudaGetSymbolAddress((void**)&xl, g_xl);
    cudaGetSymbolAddress((void**)&yh, g_yh);
    cudaGetSymbolAddress((void**)&yl, g_yl);
    cudaGetSymbolAddress((void**)&wh, g_wh);
    cudaGetSymbolAddress((void**)&wl, g_wl);
    cudaGetSymbolAddress((void**)&w2h, g_w2h);
    cudaGetSymbolAddress((void**)&w2l, g_w2l);
    cudaGetSymbolAddress((void**)&cvec, g_cvec);

    cudaFuncSetAttribute((const void*)hgemm_conv, cudaFuncAttributeMaxDynamicSharedMemorySize, SMEMDYN);
    cudaFuncSetAttribute((const void*)hgemm<16>,  cudaFuncAttributeMaxDynamicSharedMemorySize, SMEMDYN);
    cudaFuncSetAttribute((const void*)hgemm<8>,   cudaFuncAttributeMaxDynamicSharedMemorySize, SMEMDYN);

    // 1) split weights  2) split+transpose input  3) W2 = K_w^T Q_w (+ c)
    split_w3<<<(W_TOTAL + 255) / 256, 256>>>(conv_w, v_w, mlp_w);
    split_xp<<<dim3(HWP / 32, CIN / 64, NB), 256>>>(x_in);
    w2_kernel<<<dim3(8, 16), 256>>>(k_w, q_w, q_b);

    // 4) patchify conv (direct pixel-major gather) -> staging, 5) LN -> x_out
    hgemm_conv<<<dim3(TT / 128, 4, NB), 256, SMEMDYN>>>(
        xph, xpl, wh + OFF_CONV, wl + OFF_CONV, conv_b, pq);
    ln_kernel<<<NB * TT, 128>>>(pq, xh, xl, lnc_g, lnc_b, 0);

    // 6+) iterative grouping (launch #6 = qk GEMM for ncu -s 5 -c 1)
    for (int it = 0; it < ITERS; it++) {
        // qk[t] = W2 x_out[t] + c   (M=TT, N=256, K=512)
        hgemm<16><<<dim3(TT / 128, 2, NB), 256, SMEMDYN>>>(
            xh, xl, w2h, w2l, cvec, pq, TT, 256);
        // att: softmax(x_in·qk) over 2x2 window, y = Σ att·x_in
        att2_kernel<<<NB * TT / 2, 128>>>(pq, xph, xpl, yh, yl);
        // upd = V_w y + v_b   (M=TT, N=512, K=256)
        hgemm<8><<<dim3(TT / 128, 4, NB), 256, SMEMDYN>>>(
            yh, yl, wh + OFF_V, wl + OFF_V, v_b, pq, TT, CO);
        // x += LN(upd)
        ln_kernel<<<NB * TT, 128>>>(pq, xh, xl, lnv_g, lnv_b, 1);
        // mlp = M_w x + mlp_b ; x += LN(mlp)
        hgemm<16><<<dim3(TT / 128, 4, NB), 256, SMEMDYN>>>(
            xh, xl, wh + OFF_MLP, wl + OFF_MLP, mlp_b, pq, TT, CO);
        if (it < ITERS - 1) {
            ln_kernel<<<NB * TT, 128>>>(pq, xh, xl, lnm_g, lnm_b, 1);
        } else {
            // final: fused LN + residual + transpose to NCHW output
            ln_tr_kernel<<<dim3(TT / 32, 1, NB), 256>>>(pq, xh, xl, lnm_g, lnm_b, out);
        }
    }
}

// round 17
// speedup vs baseline: 1.1173x; 1.0978x over previous
#include <cuda_runtime.h>
#include <cuda_fp16.h>
#include <cstdint>

// Problem constants
#define NB   4
#define CIN  256
#define HH   128
#define WW   128
#define HWP  (HH*WW)      // 16384
#define CO   512
#define TT   4096         // 64*64 output pixels
#define EPSF 1e-5f
#define ITERS 3

// ---------------------------------------------------------------------------
// Scratch
// ---------------------------------------------------------------------------
__device__ float g_q[(size_t)NB*TT*CO];    // staging: conv/qk/upd/mlp outputs

// fp16 split operands (x_out lives ONLY as hi/lo pair; x = hi + lo to ~2^-24)
__device__ __align__(16) __half g_xph[(size_t)NB*HWP*CIN];  // x_in hi, pixel-major [b][pix][c]
__device__ __align__(16) __half g_xpl[(size_t)NB*HWP*CIN];  // x_in lo
__device__ __align__(16) __half g_xh[(size_t)NB*TT*CO];     // x_out hi, M-major [b][t][c]
__device__ __align__(16) __half g_xl[(size_t)NB*TT*CO];     // x_out lo
__device__ __align__(16) __half g_yh[(size_t)NB*TT*CIN];    // y fp16 (single), [b][t][j]
// weights: conv (reordered [n][w*256+c]) | v | mlp  ([n][k] row-major)
#define OFF_CONV 0
#define OFF_V    (512*1024)
#define OFF_MLP  (OFF_V + 512*256)
#define W_TOTAL  (OFF_MLP + 512*512)
__device__ __align__(16) __half g_wh[W_TOTAL];
__device__ __align__(16) __half g_wl[W_TOTAL];
// W2 = K_w^T Q_w (256 x 512) split, + c = K_w^T q_b
__device__ __align__(16) __half g_w2h[256*512];
__device__ __align__(16) __half g_w2l[256*512];
__device__ float g_cvec[256];

// ===========================================================================
// helpers
// ===========================================================================
__device__ __forceinline__ uint32_t smem_to_u32(const void* p) {
    uint32_t a;
    asm("{ .reg .u64 t; cvta.to.shared.u64 t, %1; cvt.u32.u64 %0, t; }"
        : "=r"(a) : "l"(p));
    return a;
}
__device__ __forceinline__ float warp_sum(float v) {
#pragma unroll
    for (int o = 16; o > 0; o >>= 1) v += __shfl_xor_sync(0xffffffffu, v, o);
    return v;
}
__device__ __forceinline__ void mma16816(float* c, const uint32_t* a, const uint32_t* b) {
    asm("mma.sync.aligned.m16n8k16.row.col.f32.f16.f16.f32 "
        "{%0,%1,%2,%3}, {%4,%5,%6,%7}, {%8,%9}, {%0,%1,%2,%3};"
        : "+f"(c[0]), "+f"(c[1]), "+f"(c[2]), "+f"(c[3])
        : "r"(a[0]), "r"(a[1]), "r"(a[2]), "r"(a[3]), "r"(b[0]), "r"(b[1]));
}
__device__ __forceinline__ void ldsm4(uint32_t* r, uint32_t a) {
    asm("ldmatrix.sync.aligned.m8n8.x4.shared.b16 {%0,%1,%2,%3}, [%4];"
        : "=r"(r[0]), "=r"(r[1]), "=r"(r[2]), "=r"(r[3]) : "r"(a) : "memory");
}
__device__ __forceinline__ void cp16(uint32_t sm, const void* g) {
    asm volatile("cp.async.cg.shared.global [%0], [%1], 16;"
        :: "r"(sm), "l"(g) : "memory");
}
__device__ __forceinline__ void cp_commit() {
    asm volatile("cp.async.commit_group;" ::: "memory");
}
template<int N> __device__ __forceinline__ void cp_wait() {
    asm volatile("cp.async.wait_group %0;" :: "n"(N) : "memory");
}
__device__ __forceinline__ void split1f(float x, __half& h, __half& l) {
    h = __float2half_rn(x);
    l = __float2half_rn(x - __half2float(h));
}
__device__ __forceinline__ void split4f(float4 f, uint2& H, uint2& L) {
    __half h[4], l[4];
    split1f(f.x, h[0], l[0]); split1f(f.y, h[1], l[1]);
    split1f(f.z, h[2], l[2]); split1f(f.w, h[3], l[3]);
    __half2 h0 = __halves2half2(h[0], h[1]), h1 = __halves2half2(h[2], h[3]);
    __half2 l0 = __halves2half2(l[0], l[1]), l1 = __halves2half2(l[2], l[3]);
    H.x = *(uint32_t*)&h0; H.y = *(uint32_t*)&h1;
    L.x = *(uint32_t*)&l0; L.y = *(uint32_t*)&l1;
}
__device__ __forceinline__ float4 join4f(uint2 H, uint2 L) {
    __half2 h0 = *(__half2*)&H.x, h1 = *(__half2*)&H.y;
    __half2 l0 = *(__half2*)&L.x, l1 = *(__half2*)&L.y;
    float4 f;
    f.x = __half2float(__low2half(h0))  + __half2float(__low2half(l0));
    f.y = __half2float(__high2half(h0)) + __half2float(__high2half(l0));
    f.z = __half2float(__low2half(h1))  + __half2float(__low2half(l1));
    f.w = __half2float(__high2half(h1)) + __half2float(__high2half(l1));
    return f;
}

// ===========================================================================
// setup kernels
// ===========================================================================
// conv region reordered: W[n][w*256+c] = conv_w[n][c*4+w]
__global__ __launch_bounds__(256)
void split_w3(const float* __restrict__ w0, const float* __restrict__ w1,
              const float* __restrict__ w2)
{
    int i = blockIdx.x * 256 + threadIdx.x;
    if (i >= W_TOTAL) return;
    const float* s; int off;
    if (i < OFF_V) {
        int n = i >> 10, k = i & 1023;
        int w = k >> 8, cc = k & 255;
        s = w0; off = n * 1024 + cc * 4 + w;
    }
    else if (i < OFF_MLP) { s = w1; off = i - OFF_V; }
    else                  { s = w2; off = i - OFF_MLP; }
    __half h, l; split1f(s[off], h, l);
    g_wh[i] = h; g_wl[i] = l;
}

// x_in (NCHW) -> pixel-major fp16 hi/lo, one pass.
__global__ __launch_bounds__(256)
void split_xp(const float* __restrict__ x)
{
    __shared__ float sm[64][33];
    const int p0 = blockIdx.x * 32;
    const int c0 = blockIdx.y * 64;
    const int b  = blockIdx.z;
    const float* xb = x + ((size_t)b * CIN + c0) * HWP + p0;
    const int tx = threadIdx.x & 31, ty = threadIdx.x >> 5;   // 32 x 8
#pragma unroll
    for (int cc = ty; cc < 64; cc += 8)
        sm[cc][tx] = xb[(size_t)cc * HWP + tx];
    __syncthreads();
    const int cp = tx, pg = ty;
#pragma unroll
    for (int p = pg; p < 32; p += 8) {
        float f0 = sm[2 * cp][p], f1 = sm[2 * cp + 1][p];
        __half h0, l0, h1, l1; split1f(f0, h0, l0); split1f(f1, h1, l1);
        __half2 H = __halves2half2(h0, h1), L = __halves2half2(l0, l1);
        size_t o = ((size_t)b * HWP + p0 + p) * CIN + c0;
        ((uint32_t*)(g_xph + o))[cp] = *(uint32_t*)&H;
        ((uint32_t*)(g_xpl + o))[cp] = *(uint32_t*)&L;
    }
}

// W2[j][f] = sum_o K_w[o][j] * Q_w[o][f], split to fp16 hi/lo; c = K_w^T q_b.
__global__ __launch_bounds__(256)
void w2_kernel(const float* __restrict__ Kw, const float* __restrict__ Qw,
               const float* __restrict__ qb)
{
    __shared__ float Ks[32][33], Qs[32][33];
    const int j0 = blockIdx.x * 32, f0 = blockIdx.y * 32;
    const int txx = threadIdx.x & 15, tyy = threadIdx.x >> 4;
    float acc[2][2] = {{0.f, 0.f}, {0.f, 0.f}};
    for (int o0 = 0; o0 < 512; o0 += 32) {
#pragma unroll
        for (int l = threadIdx.x; l < 1024; l += 256) {
            int oo = l >> 5, jj = l & 31;
            Ks[oo][jj] = Kw[(size_t)(o0 + oo) * 256 + j0 + jj];
            Qs[oo][jj] = Qw[(size_t)(o0 + oo) * 512 + f0 + jj];
        }
        __syncthreads();
#pragma unroll
        for (int oo = 0; oo < 32; ++oo) {
            float k0 = Ks[oo][tyy * 2], k1 = Ks[oo][tyy * 2 + 1];
            float q0 = Qs[oo][txx * 2], q1 = Qs[oo][txx * 2 + 1];
            acc[0][0] += k0 * q0; acc[0][1] += k0 * q1;
            acc[1][0] += k1 * q0; acc[1][1] += k1 * q1;
        }
        __syncthreads();
    }
#pragma unroll
    for (int a = 0; a < 2; a++)
#pragma unroll
        for (int bb = 0; bb < 2; bb++) {
            int j = j0 + tyy * 2 + a, f = f0 + txx * 2 + bb;
            __half h, l; split1f(acc[a][bb], h, l);
            g_w2h[(size_t)j * 512 + f] = h;
            g_w2l[(size_t)j * 512 + f] = l;
        }
    if (blockIdx.y == 0 && threadIdx.x < 32) {
        int j = j0 + threadIdx.x;
        float s = 0.f;
        for (int o = 0; o < 512; ++o) s += Kw[(size_t)o * 256 + j] * qb[o];
        g_cvec[j] = s;
    }
}

// ===========================================================================
// HMMA split-fp16 GEMM core (tile 128x128, K-chunk 32, 8 warps 2x4,
// warp tile 64x32, 3-stage cp.async, ks-split with mid-chunk issue).
// TERMS=3: hh+hl+lh (full split).  TERMS=2: hh+hl (A-lo dropped; A-lo never
// loaded from gmem or smem).
// ===========================================================================
#define STAGE   32768
#define SMEMDYN (3*STAGE)

// M-major A loader + B loader
template<int K, int TERMS>
__device__ __forceinline__ void gemm_issue(
    uint32_t sb, int s, int c, int tid, int m0, int n0,
    const __half* pAh, const __half* pAl,
    const __half* Bh, const __half* Bl)
{
    const int k0 = c * 32;
    const uint32_t As = sb + s * STAGE;
    const uint32_t Bs = As + 16384;
    if (TERMS == 3) {
#pragma unroll
        for (int j = 0; j < 4; j++) {
            int idx = tid + j * 256;
            int r = idx >> 3, q = idx & 7;
            uint32_t sm = As + r * 128 + ((q ^ (r & 7)) << 4);
            const __half* g = ((q < 4) ? pAh : pAl)
                              + (size_t)(m0 + r) * K + k0 + (q & 3) * 8;
            cp16(sm, g);
        }
    } else {
#pragma unroll
        for (int j = 0; j < 2; j++) {
            int idx = tid + j * 256;
            int r = idx >> 2, q = idx & 3;
            uint32_t sm = As + r * 128 + ((q ^ (r & 7)) << 4);
            const __half* g = pAh + (size_t)(m0 + r) * K + k0 + q * 8;
            cp16(sm, g);
        }
    }
#pragma unroll
    for (int j = 0; j < 4; j++) {
        int idx = tid + j * 256;
        int r = idx >> 3, q = idx & 7;
        uint32_t sm = Bs + r * 128 + ((q ^ (r & 7)) << 4);
        const __half* g = ((q < 4) ? Bh : Bl)
                          + (size_t)(n0 + r) * K + k0 + (q & 3) * 8;
        cp16(sm, g);
    }
    cp_commit();
}

// conv A loader (2-term: hi only): A[t][k], k = w*256 + cch, from pixel-major
// xph. pbase[j] = base of row (m0 + (tid>>2) + 64j)'s top-left window pixel.
__device__ __forceinline__ void gemm_issue_conv(
    uint32_t sb, int s, int c, int tid,
    const size_t* pbase,               // [2]
    const __half* xph,
    const __half* Bh, const __half* Bl, int n0)
{
    const int k0 = c * 32;
    const int w = c >> 3;              // window pixel index 0..3
    const size_t woff = (size_t)(w >> 1) * ((size_t)WW * CIN)
                      + (size_t)(w & 1) * CIN;
    const int cb = (c & 7) * 32;       // channel base within pixel
    const uint32_t As = sb + s * STAGE;
    const uint32_t Bs = As + 16384;
#pragma unroll
    for (int j = 0; j < 2; j++) {
        int idx = tid + j * 256;
        int r = idx >> 2, q = idx & 3;   // r = (tid>>2) + 64j
        uint32_t sm = As + r * 128 + ((q ^ (r & 7)) << 4);
        const __half* g = xph + pbase[j] + woff + cb + q * 8;
        cp16(sm, g);
    }
#pragma unroll
    for (int j = 0; j < 4; j++) {
        int idx = tid + j * 256;
        int r = idx >> 3, q = idx & 7;
        uint32_t sm = Bs + r * 128 + ((q ^ (r & 7)) << 4);
        const __half* g = ((q < 4) ? Bh : Bl)
                          + (size_t)(n0 + r) * 1024 + k0 + (q & 3) * 8;
        cp16(sm, g);
    }
    cp_commit();
}

// R13 form compute: all A fragments up-front (M-major GEMMs).
template<int KS, int TERMS>
__device__ __forceinline__ void gemm_compute_ks(
    uint32_t sb, int s, int lane, int wm, int wn, float acc[4][4][4])
{
    const uint32_t As = sb + s * STAGE;
    const uint32_t Bs = As + 16384;
    const int g = lane >> 3;
    const uint32_t l7 = lane & 7;
    uint32_t bh[8], bl[8], ah[16], al[16];
    {
        uint32_t nrow = wn * 32 + (g >> 1) * 8 + l7;
        uint32_t cH = ((KS * 2 + (g & 1)) ^ l7) << 4;
        uint32_t cL = ((KS * 2 + (g & 1) + 4) ^ l7) << 4;
        uint32_t r0 = Bs + nrow * 128;
        ldsm4(&bh[0], r0 + cH);
        ldsm4(&bl[0], r0 + cL);
        uint32_t r1 = r0 + 16 * 128;
        ldsm4(&bh[4], r1 + cH);
        ldsm4(&bl[4], r1 + cL);
    }
#pragma unroll
    for (int mt = 0; mt < 4; ++mt) {
        uint32_t mrow = wm * 64 + mt * 16 + (g & 1) * 8 + l7;
        uint32_t ch = KS * 2 + (g >> 1);
        uint32_t ra = As + mrow * 128;
        ldsm4(&ah[mt * 4], ra + ((ch ^ l7) << 4));
        if (TERMS == 3) ldsm4(&al[mt * 4], ra + (((ch + 4) ^ l7) << 4));
    }
#pragma unroll
    for (int mt = 0; mt < 4; ++mt)
#pragma unroll
        for (int nt = 0; nt < 4; ++nt) mma16816(acc[mt][nt], &ah[mt * 4], &bh[nt * 2]);
#pragma unroll
    for (int mt = 0; mt < 4; ++mt)
#pragma unroll
        for (int nt = 0; nt < 4; ++nt) mma16816(acc[mt][nt], &ah[mt * 4], &bl[nt * 2]);
    if (TERMS == 3) {
#pragma unroll
        for (int mt = 0; mt < 4; ++mt)
#pragma unroll
            for (int nt = 0; nt < 4; ++nt) mma16816(acc[mt][nt], &al[mt * 4], &bh[nt * 2]);
    }
}

// mt-pipelined form (conv; 2-term).
template<int KS>
__device__ __forceinline__ void gemm_compute_ks_mt2(
    uint32_t sb, int s, int lane, int wm, int wn, float acc[4][4][4])
{
    const uint32_t As = sb + s * STAGE;
    const uint32_t Bs = As + 16384;
    const int g = lane >> 3;
    const uint32_t l7 = lane & 7;
    uint32_t bh[8], bl[8], ah[16];
    {
        uint32_t nrow = wn * 32 + (g >> 1) * 8 + l7;
        uint32_t cH = ((KS * 2 + (g & 1)) ^ l7) << 4;
        uint32_t cL = ((KS * 2 + (g & 1) + 4) ^ l7) << 4;
        uint32_t r0 = Bs + nrow * 128;
        ldsm4(&bh[0], r0 + cH);
        ldsm4(&bl[0], r0 + cL);
        uint32_t r1 = r0 + 16 * 128;
        ldsm4(&bh[4], r1 + cH);
        ldsm4(&bl[4], r1 + cL);
    }
    const uint32_t ch = KS * 2 + (g >> 1);
    auto loadA = [&](int mt) {
        uint32_t mrow = wm * 64 + mt * 16 + (g & 1) * 8 + l7;
        uint32_t ra = As + mrow * 128;
        ldsm4(&ah[mt * 4], ra + ((ch ^ l7) << 4));
    };
    loadA(0);
#pragma unroll
    for (int mt = 0; mt < 4; ++mt) {
        if (mt < 3) loadA(mt + 1);
#pragma unroll
        for (int nt = 0; nt < 4; ++nt) mma16816(acc[mt][nt], &ah[mt * 4], &bh[nt * 2]);
    }
#pragma unroll
    for (int mt = 0; mt < 4; ++mt)
#pragma unroll
        for (int nt = 0; nt < 4; ++nt) mma16816(acc[mt][nt], &ah[mt * 4], &bl[nt * 2]);
}

__device__ __forceinline__ void gemm_epilogue(
    float acc[4][4][4], const float* bias, float* C,
    int lane, int wm, int wn, int m0, int n0, size_t bM, int ldc)
{
    const int gq = lane >> 2, tq = lane & 3;
#pragma unroll
    for (int mt = 0; mt < 4; ++mt) {
        int mrow = m0 + wm * 64 + mt * 16 + gq;
        float* Cr = C + (bM + mrow) * ldc + n0;
#pragma unroll
        for (int nt = 0; nt < 4; ++nt) {
            int col = wn * 32 + nt * 8 + tq * 2;
            float b0 = bias[n0 + col], b1 = bias[n0 + col + 1];
            float2 v0; v0.x = acc[mt][nt][0] + b0; v0.y = acc[mt][nt][1] + b1;
            *(float2*)&Cr[col] = v0;
            float2 v1; v1.x = acc[mt][nt][2] + b0; v1.y = acc[mt][nt][3] + b1;
            *(float2*)&Cr[col + 8 * ldc] = v1;
        }
    }
}

template<int NCH, int TERMS>
__global__ __launch_bounds__(256, 2)
void hgemm(const __half* __restrict__ Ah, const __half* __restrict__ Al,
           const __half* __restrict__ Bh, const __half* __restrict__ Bl,
           const float* __restrict__ bias, float* __restrict__ C,
           int M, int ldc)
{
    constexpr int K = NCH * 32;
    extern __shared__ char sm_[];
    const uint32_t sb = smem_to_u32(sm_);
    const int tid = threadIdx.x;
    const int lane = tid & 31;
    const int wid = tid >> 5;
    const int wm = wid & 1, wn = wid >> 1;
    const int m0 = blockIdx.x * 128, n0 = blockIdx.y * 128, bz = blockIdx.z;
    const __half* pAh = Ah + (size_t)bz * M * K;
    const __half* pAl = Al + (size_t)bz * M * K;

    float acc[4][4][4];
#pragma unroll
    for (int i = 0; i < 4; i++)
#pragma unroll
        for (int j = 0; j < 4; j++)
#pragma unroll
            for (int r = 0; r < 4; r++) acc[i][j][r] = 0.f;

    gemm_issue<K, TERMS>(sb, 0, 0, tid, m0, n0, pAh, pAl, Bh, Bl);
    gemm_issue<K, TERMS>(sb, 1, 1, tid, m0, n0, pAh, pAl, Bh, Bl);
#pragma unroll
    for (int c = 0; c < NCH; ++c) {
        if (c < NCH - 1) cp_wait<1>(); else cp_wait<0>();
        __syncthreads();
        gemm_compute_ks<0, TERMS>(sb, c % 3, lane, wm, wn, acc);
        if (c + 2 < NCH) gemm_issue<K, TERMS>(sb, (c + 2) % 3, c + 2, tid, m0, n0, pAh, pAl, Bh, Bl);
        gemm_compute_ks<1, TERMS>(sb, c % 3, lane, wm, wn, acc);
    }
    gemm_epilogue(acc, bias, C, lane, wm, wn, m0, n0, (size_t)bz * M, ldc);
}

// conv GEMM: 2-term, A gathered from pixel-major x_in hi (k = w*256 + c), K=1024.
__global__ __launch_bounds__(256, 2)
void hgemm_conv(const __half* __restrict__ xph,
                const __half* __restrict__ Bh, const __half* __restrict__ Bl,
                const float* __restrict__ bias, float* __restrict__ C)
{
    constexpr int NCH = 32;
    extern __shared__ char sm_[];
    const uint32_t sb = smem_to_u32(sm_);
    const int tid = threadIdx.x;
    const int lane = tid & 31;
    const int wid = tid >> 5;
    const int wm = wid & 1, wn = wid >> 1;
    const int m0 = blockIdx.x * 128, n0 = blockIdx.y * 128, bz = blockIdx.z;

    // per-j (2 A rows per thread: r = tid>>2 + 64j) top-left pixel bases
    size_t pbase[2];
    {
        int r0 = tid >> 2;
#pragma unroll
        for (int j = 0; j < 2; ++j) {
            int t = m0 + r0 + j * 64, ho = t >> 6, wo = t & 63;
            int pix = (ho << 1) * WW + (wo << 1);
            pbase[j] = ((size_t)bz * HWP + pix) * CIN;
        }
    }

    float acc[4][4][4];
#pragma unroll
    for (int i = 0; i < 4; i++)
#pragma unroll
        for (int j = 0; j < 4; j++)
#pragma unroll
            for (int r = 0; r < 4; r++) acc[i][j][r] = 0.f;

    gemm_issue_conv(sb, 0, 0, tid, pbase, xph, Bh, Bl, n0);
    gemm_issue_conv(sb, 1, 1, tid, pbase, xph, Bh, Bl, n0);
#pragma unroll
    for (int c = 0; c < NCH; ++c) {
        if (c < NCH - 1) cp_wait<1>(); else cp_wait<0>();
        __syncthreads();
        gemm_compute_ks_mt2<0>(sb, c % 3, lane, wm, wn, acc);
        if (c + 2 < NCH) gemm_issue_conv(sb, (c + 2) % 3, c + 2, tid, pbase, xph, Bh, Bl, n0);
        gemm_compute_ks_mt2<1>(sb, c % 3, lane, wm, wn, acc);
    }
    gemm_epilogue(acc, bias, C, lane, wm, wn, m0, n0, (size_t)bz * TT, CO);
}

// ---------------------------------------------------------------------------
// Channel LayerNorm over CO=512, float4-vectorized, 128 threads/row.
// x_out lives as fp16 hi/lo pair; add-path reconstructs x = hi + lo.
// ---------------------------------------------------------------------------
__global__ __launch_bounds__(128)
void ln_kernel(const float* __restrict__ in,
               __half* __restrict__ xh, __half* __restrict__ xl,
               const float* __restrict__ g, const float* __restrict__ bvec, int add)
{
    const int tid = threadIdx.x;
    const size_t row = blockIdx.x;
    float4 v = ((const float4*)(in + row * CO))[tid];
    float s  = v.x + v.y + v.z + v.w;
    float s2 = v.x * v.x + v.y * v.y + v.z * v.z + v.w * v.w;
    s  = warp_sum(s);
    s2 = warp_sum(s2);
    __shared__ float r1[4], r2[4];
    const int lane = tid & 31, warp = tid >> 5;
    if (lane == 0) { r1[warp] = s; r2[warp] = s2; }
    __syncthreads();
    float ss = r1[0] + r1[1] + r1[2] + r1[3];
    float sq = r2[0] + r2[1] + r2[2] + r2[3];
    float mu  = ss / CO;
    float var = sq / CO - mu * mu;
    float rs  = rsqrtf(var + EPSF);
    float4 g4 = ((const float4*)g)[tid];
    float4 b4 = ((const float4*)bvec)[tid];
    float4 f;
    f.x = (v.x - mu) * rs * g4.x + b4.x;
    f.y = (v.y - mu) * rs * g4.y + b4.y;
    f.z = (v.z - mu) * rs * g4.z + b4.z;
    f.w = (v.w - mu) * rs * g4.w + b4.w;
    uint2* ph = (uint2*)(xh + row * CO);
    uint2* pl = (uint2*)(xl + row * CO);
    if (add) {
        float4 o = join4f(ph[tid], pl[tid]);
        f.x += o.x; f.y += o.y; f.z += o.z; f.w += o.w;
    }
    uint2 H, L; split4f(f, H, L);
    ph[tid] = H;
    pl[tid] = L;
}

// ---------------------------------------------------------------------------
// Fused FINAL LayerNorm + residual + transpose to NCHW fp32 output.
// ---------------------------------------------------------------------------
__global__ __launch_bounds__(256)
void ln_tr_kernel(const float* __restrict__ in,
                  const __half* __restrict__ xh, const __half* __restrict__ xl,
                  const float* __restrict__ g, const float* __restrict__ bvec,
                  float* __restrict__ out)
{
    __shared__ float smu[32], srs[32], tile[32][33];
    const int b  = blockIdx.z;
    const int t0 = blockIdx.x * 32;
    const int tid = threadIdx.x;
    const int lane = tid & 31, warp = tid >> 5;

    // Phase A: stats for 32 rows, warp w handles rows 4w..4w+3
#pragma unroll
    for (int rr = 0; rr < 4; ++rr) {
        int r = warp * 4 + rr;
        const float4* row = (const float4*)(in + ((size_t)b * TT + t0 + r) * CO);
        float s = 0.f, s2 = 0.f;
#pragma unroll
        for (int i = 0; i < 4; ++i) {
            float4 v = row[lane + 32 * i];
            s  += v.x + v.y + v.z + v.w;
            s2 += v.x * v.x + v.y * v.y + v.z * v.z + v.w * v.w;
        }
        s = warp_sum(s); s2 = warp_sum(s2);
        if (lane == 0) {
            float mu = s / CO, var = s2 / CO - mu * mu;
            smu[r] = mu; srs[r] = rsqrtf(var + EPSF);
        }
    }
    __syncthreads();

    // Phase B: 16 f-tiles of 32
    const int tx = tid & 31, ty = tid >> 5;   // 32 x 8
    for (int f0 = 0; f0 < CO; f0 += 32) {
        float gg = g[f0 + tx], bb = bvec[f0 + tx];
#pragma unroll
        for (int j = 0; j < 32; j += 8) {
            int r = ty + j;
            size_t o = ((size_t)b * TT + t0 + r) * CO + f0 + tx;
            float xo = __half2float(xh[o]) + __half2float(xl[o]);
            tile[r][tx] = xo + (in[o] - smu[r]) * srs[r] * gg + bb;
        }
        __syncthreads();
#pragma unroll
        for (int j = 0; j < 32; j += 8)
            out[((size_t)b * CO + f0 + ty + j) * TT + t0 + tx] = tile[tx][ty + j];
        __syncthreads();
    }
}

// ---------------------------------------------------------------------------
// Attention core: 2 rows per 128-thread block, 64 threads/row, 4 ch/thread.
// y written as plain fp16 (upd GEMM is 2-term; y-lo not needed).
// ---------------------------------------------------------------------------
__global__ __launch_bounds__(128)
void att2_kernel(const float* __restrict__ qk,
                 const __half* __restrict__ xph, const __half* __restrict__ xpl,
                 __half* __restrict__ yh)
{
    const int tid = threadIdx.x;
    const int rid = tid >> 6, lt = tid & 63;
    const int row = blockIdx.x * 2 + rid;       // b*T + t
    const int b = row >> 12;
    const int t = row & (TT - 1);
    const int ho = t >> 6, wo = t & 63;
    const int pix0 = (ho << 1) * WW + (wo << 1);
    const size_t base = ((size_t)b * HWP + pix0) * CIN + 4 * lt;

    const float4 q4 = ((const float4*)(qk + (size_t)row * 256))[lt];

    float xv[4][4];
    const size_t offs[4] = {0, CIN, (size_t)WW * CIN, (size_t)WW * CIN + CIN};
#pragma unroll
    for (int w = 0; w < 4; ++w) {
        uint2 H = *(const uint2*)(xph + base + offs[w]);
        uint2 L = *(const uint2*)(xpl + base + offs[w]);
        float4 f = join4f(H, L);
        xv[w][0] = f.x; xv[w][1] = f.y; xv[w][2] = f.z; xv[w][3] = f.w;
    }
    float d[4];
#pragma unroll
    for (int w = 0; w < 4; ++w) {
        d[w] = q4.x * xv[w][0] + q4.y * xv[w][1] + q4.z * xv[w][2] + q4.w * xv[w][3];
        d[w] = warp_sum(d[w]);
    }
    __shared__ float red[2][4][2];
    const int lane = tid & 31, wp = (tid >> 5) & 1;
    if (lane == 0) {
        red[rid][0][wp] = d[0]; red[rid][1][wp] = d[1];
        red[rid][2][wp] = d[2]; red[rid][3][wp] = d[3];
    }
    __syncthreads();
    float a0 = red[rid][0][0] + red[rid][0][1];
    float a1 = red[rid][1][0] + red[rid][1][1];
    float a2 = red[rid][2][0] + red[rid][2][1];
    float a3 = red[rid][3][0] + red[rid][3][1];
    float mx = fmaxf(fmaxf(a0, a1), fmaxf(a2, a3));
    float e0 = __expf(a0 - mx), e1 = __expf(a1 - mx);
    float e2 = __expf(a2 - mx), e3 = __expf(a3 - mx);
    float inv = 1.f / (e0 + e1 + e2 + e3);
    e0 *= inv; e1 *= inv; e2 *= inv; e3 *= inv;

    float4 yv;
    yv.x = e0 * xv[0][0] + e1 * xv[1][0] + e2 * xv[2][0] + e3 * xv[3][0];
    yv.y = e0 * xv[0][1] + e1 * xv[1][1] + e2 * xv[2][1] + e3 * xv[3][1];
    yv.z = e0 * xv[0][2] + e1 * xv[1][2] + e2 * xv[2][2] + e3 * xv[3][2];
    yv.w = e0 * xv[0][3] + e1 * xv[1][3] + e2 * xv[2][3] + e3 * xv[3][3];
    __half2 y0 = __halves2half2(__float2half_rn(yv.x), __float2half_rn(yv.y));
    __half2 y1 = __halves2half2(__float2half_rn(yv.z), __float2half_rn(yv.w));
    uint2 Y; Y.x = *(uint32_t*)&y0; Y.y = *(uint32_t*)&y1;
    *(uint2*)(yh + (size_t)row * 256 + 4 * lt) = Y;
}

// ---------------------------------------------------------------------------
extern "C" void kernel_launch(void* const* d_in, const int* in_sizes, int n_in,
                              void* d_out, int out_size)
{
    const float* x_in   = (const float*)d_in[0];
    const float* conv_w = (const float*)d_in[1];
    const float* conv_b = (const float*)d_in[2];
    const float* k_w    = (const float*)d_in[3];
    const float* k_b    = (const float*)d_in[4];   // const over window -> drops in softmax
    const float* q_w    = (const float*)d_in[5];
    const float* q_b    = (const float*)d_in[6];
    const float* v_w    = (const float*)d_in[7];
    const float* v_b    = (const float*)d_in[8];
    const float* mlp_w  = (const float*)d_in[9];
    const float* mlp_b  = (const float*)d_in[10];
    const float* lnc_g  = (const float*)d_in[11];
    const float* lnc_b  = (const float*)d_in[12];
    const float* lnv_g  = (const float*)d_in[13];
    const float* lnv_b  = (const float*)d_in[14];
    const float* lnm_g  = (const float*)d_in[15];
    const float* lnm_b  = (const float*)d_in[16];
    float* out = (float*)d_out;
    (void)k_b;

    float *pq, *cvec;
    __half *xph, *xpl, *xh, *xl, *yh, *wh, *wl, *w2h, *w2l;
    cudaGetSymbolAddress((void**)&pq, g_q);
    cudaGetSymbolAddress((void**)&xph, g_xph);
    cudaGetSymbolAddress((void**)&xpl, g_xpl);
    cudaGetSymbolAddress((void**)&xh, g_xh);
    cudaGetSymbolAddress((void**)&xl, g_xl);
    cudaGetSymbolAddress((void**)&yh, g_yh);
    cudaGetSymbolAddress((void**)&wh, g_wh);
    cudaGetSymbolAddress((void**)&wl, g_wl);
    cudaGetSymbolAddress((void**)&w2h, g_w2h);
    cudaGetSymbolAddress((void**)&w2l, g_w2l);
    cudaGetSymbolAddress((void**)&cvec, g_cvec);

    cudaFuncSetAttribute((const void*)hgemm_conv,  cudaFuncAttributeMaxDynamicSharedMemorySize, SMEMDYN);
    cudaFuncSetAttribute((const void*)hgemm<16,3>, cudaFuncAttributeMaxDynamicSharedMemorySize, SMEMDYN);
    cudaFuncSetAttribute((const void*)hgemm<8,2>,  cudaFuncAttributeMaxDynamicSharedMemorySize, SMEMDYN);

    // 1) split weights  2) split+transpose input  3) W2 = K_w^T Q_w (+ c)
    split_w3<<<(W_TOTAL + 255) / 256, 256>>>(conv_w, v_w, mlp_w);
    split_xp<<<dim3(HWP / 32, CIN / 64, NB), 256>>>(x_in);
    w2_kernel<<<dim3(8, 16), 256>>>(k_w, q_w, q_b);

    // 4) patchify conv (2-term, hi-only gather) -> staging, 5) LN -> x_out
    hgemm_conv<<<dim3(TT / 128, 4, NB), 256, SMEMDYN>>>(
        xph, wh + OFF_CONV, wl + OFF_CONV, conv_b, pq);
    ln_kernel<<<NB * TT, 128>>>(pq, xh, xl, lnc_g, lnc_b, 0);

    // 6+) iterative grouping (launch #6 = qk GEMM for ncu -s 5 -c 1)
    for (int it = 0; it < ITERS; it++) {
        // qk[t] = W2 x_out[t] + c   (M=TT, N=256, K=512), 3-term
        hgemm<16,3><<<dim3(TT / 128, 2, NB), 256, SMEMDYN>>>(
            xh, xl, w2h, w2l, cvec, pq, TT, 256);
        // att: softmax(x_in·qk) over 2x2 window, y = Σ att·x_in (fp16)
        att2_kernel<<<NB * TT / 2, 128>>>(pq, xph, xpl, yh);
        // upd = V_w y + v_b   (M=TT, N=512, K=256), 2-term (y fp16)
        hgemm<8,2><<<dim3(TT / 128, 4, NB), 256, SMEMDYN>>>(
            yh, yh, wh + OFF_V, wl + OFF_V, v_b, pq, TT, CO);
        // x += LN(upd)
        ln_kernel<<<NB * TT, 128>>>(pq, xh, xl, lnv_g, lnv_b, 1);
        // mlp = M_w x + mlp_b (3-term) ; x += LN(mlp)
        hgemm<16,3><<<dim3(TT / 128, 4, NB), 256, SMEMDYN>>>(
            xh, xl, wh + OFF_MLP, wl + OFF_MLP, mlp_b, pq, TT, CO);
        if (it < ITERS - 1) {
            ln_kernel<<<NB * TT, 128>>>(pq, xh, xl, lnm_g, lnm_b, 1);
        } else {
            // final: fused LN + residual + transpose to NCHW output
            ln_tr_kernel<<<dim3(TT / 32, 1, NB), 256>>>(pq, xh, xl, lnm_g, lnm_b, out);
        }
    }
}